// round 3
// baseline (speedup 1.0000x reference)
#include <cuda_runtime.h>
#include <math.h>

#define LDP 65          // padded point-stride for smem activation rows
#define WCAP 8192       // weight staging buffer, floats (32KB)
#define NT 512          // threads per CTA

typedef unsigned long long ull;

// ---------------- f32x2 packed-FMA helpers (sm_100+ only PTX path) ----------
__device__ __forceinline__ ull dup2(float a) {
    ull r; unsigned u = __float_as_uint(a);
    asm("mov.b64 %0, {%1, %1};" : "=l"(r) : "r"(u));
    return r;
}
__device__ __forceinline__ void ffma2(ull& d, ull a, ull b) {
    asm("fma.rn.f32x2 %0, %1, %2, %0;" : "+l"(d) : "l"(a), "l"(b));
}
__device__ __forceinline__ float2 unpk(ull v) {
    unsigned lo, hi;
    asm("mov.b64 {%0, %1}, %2;" : "=r"(lo), "=r"(hi) : "l"(v));
    return make_float2(__uint_as_float(lo), __uint_as_float(hi));
}

// ---------------- bilinear sampler setup (grid_sample semantics) ------------
__device__ __forceinline__ void make_sampler(float gx, float gy, int Ws, int Hs, int p,
                                             int* o, float* w)
{
    float xf = fmaf(gx + 1.f, 0.5f * (float)Ws, -0.5f);
    float yf = fmaf(gy + 1.f, 0.5f * (float)Hs, -0.5f);
    float x0f = floorf(xf), y0f = floorf(yf);
    int x0 = (int)x0f, y0 = (int)y0f;
    int ix0 = min(max(x0,     0), Ws - 1);
    int ix1 = min(max(x0 + 1, 0), Ws - 1);
    int iy0 = min(max(y0,     0), Hs - 1);
    int iy1 = min(max(y0 + 1, 0), Hs - 1);
    o[p]       = iy0 * Ws + ix0;
    o[64 + p]  = iy0 * Ws + ix1;
    o[128 + p] = iy1 * Ws + ix0;
    o[192 + p] = iy1 * Ws + ix1;
    w[p]      = xf - x0f;
    w[64 + p] = yf - y0f;
}

// ---------------- gather C channels for 64 points into smem [C][LDP] --------
template<int C, int HWs>
__device__ __forceinline__ void sample_fm(const float* __restrict__ fm,
                                          const int* __restrict__ o,
                                          const float* __restrict__ w,
                                          float* __restrict__ dst)
{
    const int tid = threadIdx.x;
    for (int t = tid; t < C * 64; t += NT) {
        const int p = t & 63, c = t >> 6;
        const float* f = fm + c * HWs;
        float v00 = f[o[p]],       v01 = f[o[64 + p]];
        float v10 = f[o[128 + p]], v11 = f[o[192 + p]];
        float fx = w[p], fy = w[64 + p];
        float va = fmaf(fx, v01 - v00, v00);
        float vb = fmaf(fx, v11 - v10, v10);
        dst[c * LDP + p] = fmaf(fy, vb - va, va);
    }
}

// ---------------- generic dense layer: out[N][64] = W^T in[K][64] + b -------
// Weights W row-major [K][N]; staged in K-chunks into smem; each thread owns
// an 8-wide j block for one point p, accumulating with packed f32x2 FMAs.
template<int K, int N>
__device__ __forceinline__ void dense(const float* __restrict__ W,
                                      const float* __restrict__ bias,
                                      const float* __restrict__ inS,
                                      float* __restrict__ outS,
                                      float* __restrict__ ws)
{
    const int tid = threadIdx.x;
    for (int idx = tid; idx < N * 64; idx += NT)
        outS[(idx >> 6) * LDP + (idx & 63)] = bias[idx >> 6];
    __syncthreads();

    const int p  = tid & 63;
    const int jg = tid >> 6;           // 0..7
    constexpr int KC = (WCAP / N < K) ? (WCAP / N) : K;

    for (int k0 = 0; k0 < K; k0 += KC) {
        const int kc = (K - k0 < KC) ? (K - k0) : KC;
        {   // stage weight chunk (float4, fully coalesced)
            const float4* src = (const float4*)(W + k0 * N);
            float4* dst = (float4*)ws;
            const int n4 = (kc * N) >> 2;
            for (int idx = tid; idx < n4; idx += NT) dst[idx] = src[idx];
        }
        __syncthreads();

        for (int jb = jg * 8; jb < N; jb += 64) {
            ull a0 = 0, a1 = 0, a2v = 0, a3 = 0;
            const float* ip = inS + k0 * LDP + p;
            const ulonglong2* wp = (const ulonglong2*)(ws + jb);
            #pragma unroll 4
            for (int kk = 0; kk < kc; ++kk) {
                ull av = dup2(ip[kk * LDP]);
                ulonglong2 w01 = wp[0];
                ulonglong2 w23 = wp[1];
                ffma2(a0,  av, w01.x);
                ffma2(a1,  av, w01.y);
                ffma2(a2v, av, w23.x);
                ffma2(a3,  av, w23.y);
                wp += N / 4;   // one K row = N floats = N/4 ulonglong2
            }
            float* op = outS + jb * LDP + p;
            float2 v;
            v = unpk(a0);  op[0 * LDP] += v.x; op[1 * LDP] += v.y;
            v = unpk(a1);  op[2 * LDP] += v.x; op[3 * LDP] += v.y;
            v = unpk(a2v); op[4 * LDP] += v.x; op[5 * LDP] += v.y;
            v = unpk(a3);  op[6 * LDP] += v.x; op[7 * LDP] += v.y;
        }
        __syncthreads();
    }
}

// ---------------- elementwise epilogues -------------------------------------
__device__ __forceinline__ void epi_gelu(float* buf, int N) {
    const int tid = threadIdx.x;
    for (int idx = tid; idx < N * 64; idx += NT) {
        float* a = buf + (idx >> 6) * LDP + (idx & 63);
        float v = *a;
        *a = 0.5f * v * (1.f + erff(v * 0.70710678118654752f));
    }
}
__device__ __forceinline__ void epi_relu(float* buf, int N) {
    const int tid = threadIdx.x;
    for (int idx = tid; idx < N * 64; idx += NT) {
        float* a = buf + (idx >> 6) * LDP + (idx & 63);
        *a = fmaxf(*a, 0.f);
    }
}
__device__ __forceinline__ void epi_res(float* out, const float* res, const float* sg) {
    const int tid = threadIdx.x;
    for (int idx = tid; idx < 128 * 64; idx += NT) {
        int j = idx >> 6, p = idx & 63;
        out[j * LDP + p] = res[j * LDP + p] + sg[j] * out[j * LDP + p];
    }
}

// ---------------- fused kernel ----------------------------------------------
// smem layout (floats):
//   bufA [260][65] | bufB [260][65] | fbuf [128][65] | ws [8192] | aux [1536]
#define SMEM_FLOATS (2*260*LDP + 128*LDP + WCAP + 1536)

__global__ __launch_bounds__(NT, 1)
void ifd_kernel(const float* __restrict__ feat_s8,
                const float* __restrict__ feat1_s8,
                const float* __restrict__ feat_s16,
                const float* __restrict__ ctx_s8,
                const float* __restrict__ coarse_flow,
                const float* __restrict__ proj_ctx_w, const float* __restrict__ proj_ctx_b,
                const float* __restrict__ gate1,
                const float* __restrict__ ffn1_w1, const float* __restrict__ ffn1_b1,
                const float* __restrict__ ffn1_w2, const float* __restrict__ ffn1_b2,
                const float* __restrict__ proj_s8_w, const float* __restrict__ proj_s8_b,
                const float* __restrict__ gate2,
                const float* __restrict__ ffn2_w1, const float* __restrict__ ffn2_b1,
                const float* __restrict__ ffn2_w2, const float* __restrict__ ffn2_b2,
                const float* __restrict__ hw0, const float* __restrict__ hb0,
                const float* __restrict__ hw1, const float* __restrict__ hb1,
                const float* __restrict__ hw2, const float* __restrict__ hb2,
                const float* __restrict__ hw3, const float* __restrict__ hb3,
                float* __restrict__ out)
{
    extern __shared__ float sm[];
    float* bufA = sm;
    float* bufB = sm + 260 * LDP;
    float* fbuf = sm + 2 * 260 * LDP;
    float* ws   = fbuf + 128 * LDP;
    float* aux  = ws + WCAP;

    int*   s8o  = (int*)aux;            // 256 ints
    float* s8w  = aux + 256;            // 128
    int*   s16o = (int*)(aux + 384);    // 256
    float* s16w = aux + 640;            // 128
    int*   wro  = (int*)(aux + 768);    // 256
    float* wrw  = aux + 1024;           // 128
    float* sg1  = aux + 1152;           // 128
    float* sg2  = aux + 1280;           // 128
    float* cqxA = aux + 1408;           // 64
    float* cqyA = aux + 1472;           // 64

    const int tid = threadIdx.x;
    const int blk = blockIdx.x;
    const int b = (blk >= 3072) ? 1 : 0;       // 3072 tiles per batch
    const int t = blk - b * 3072;
    const int yrow  = t >> 3;
    const int xbase = (t & 7) << 6;

    const float* f8b  = feat_s8     + (size_t)b * 128 * 3072;
    const float* f1b  = feat1_s8    + (size_t)b * 128 * 3072;
    const float* f16b = feat_s16    + (size_t)b * 128 * 768;
    const float* cxb  = ctx_s8      + (size_t)b * 64  * 3072;
    const float* cfb  = coarse_flow + (size_t)b * 2   * 3072;

    // ---- phase 0: per-point samplers, coarse flow, warp coords -------------
    if (tid < 64) {
        const int p = tid;
        const float lim = 1.f - 1e-6f;
        float gx = (2.f * (float)(xbase + p) + 1.f) * (1.f / 512.f) - 1.f;
        float gy = (2.f * (float)yrow + 1.f) * (1.f / 384.f) - 1.f;
        gx = fminf(fmaxf(gx, -lim), lim);
        gy = fminf(fmaxf(gy, -lim), lim);
        make_sampler(gx, gy, 64, 48, p, s8o, s8w);
        make_sampler(gx, gy, 32, 24, p, s16o, s16w);

        float fx = s8w[p], fy = s8w[64 + p];
        int o00 = s8o[p], o01 = s8o[64 + p], o10 = s8o[128 + p], o11 = s8o[192 + p];
        float c0, c1;
        {
            const float* f = cfb;
            float va = fmaf(fx, f[o01] - f[o00], f[o00]);
            float vb = fmaf(fx, f[o11] - f[o10], f[o10]);
            c0 = fmaf(fy, vb - va, va);
            f = cfb + 3072;
            va = fmaf(fx, f[o01] - f[o00], f[o00]);
            vb = fmaf(fx, f[o11] - f[o10], f[o10]);
            c1 = fmaf(fy, vb - va, va);
        }
        float cqx = 8.f * c0, cqy = 8.f * c1;      // coarse_at_q (scale = [8,8])
        cqxA[p] = cqx; cqyA[p] = cqy;
        float wxn = fminf(fmaxf(gx + cqx * (2.f / 512.f), -lim), lim);
        float wyn = fminf(fmaxf(gy + cqy * (2.f / 384.f), -lim), lim);
        make_sampler(wxn, wyn, 64, 48, p, wro, wrw);

        // mlp_in tail rows (written once; rows 256..259 never touched by GEMMs)
        bufA[256 * LDP + p] = gx;
        bufA[257 * LDP + p] = gy;
        bufA[258 * LDP + p] = cqx * (1.f / 512.f);
        bufA[259 * LDP + p] = cqy * (1.f / 384.f);
    }
    if (tid < 128) {
        sg1[tid] = 1.f / (1.f + expf(-gate1[tid]));
        sg2[tid] = 1.f / (1.f + expf(-gate2[tid]));
    }
    __syncthreads();

    // ---- sampling: fctx -> bufA[0..63], f8 -> fbuf -------------------------
    sample_fm<64, 3072>(cxb, s8o, s8w, bufA);
    sample_fm<128, 3072>(f8b, s8o, s8w, fbuf);
    __syncthreads();

    // ---- L1: h1 = f8 + sg1 * (fctx @ proj_ctx_w + b) -> bufB[0..127] -------
    dense<64, 128>(proj_ctx_w, proj_ctx_b, bufA, bufB, ws);
    epi_res(bufB, fbuf, sg1);
    __syncthreads();

    // f16 -> fbuf (f8 is dead now)
    sample_fm<128, 768>(f16b, s16o, s16w, fbuf);
    __syncthreads();

    // ---- L2/L3: h2 = (gelu(h1 @ w1 + b)) @ w2 + b --------------------------
    dense<128, 256>(ffn1_w1, ffn1_b1, bufB, bufA, ws);
    epi_gelu(bufA, 256);
    __syncthreads();
    dense<256, 128>(ffn1_w2, ffn1_b2, bufA, bufB, ws);

    // f1_warped -> bufA rows 128..255 (bufA input just consumed; rows 0..127
    // will be rewritten by L4)
    sample_fm<128, 3072>(f1b, wro, wrw, bufA + 128 * LDP);
    __syncthreads();

    // ---- L4: h3 = f16 + sg2 * (h2 @ proj_s8_w + b) -> bufA[0..127] ---------
    dense<128, 128>(proj_s8_w, proj_s8_b, bufB, bufA, ws);
    epi_res(bufA, fbuf, sg2);
    __syncthreads();

    // ---- L5/L6: fused = (gelu(h3 @ w1 + b)) @ w2 + b -> bufA[0..127] -------
    dense<128, 256>(ffn2_w1, ffn2_b1, bufA, bufB, ws);
    epi_gelu(bufB, 256);
    __syncthreads();
    dense<256, 128>(ffn2_w2, ffn2_b2, bufB, bufA, ws);
    // bufA now holds mlp_in: [fused(0..127) | f1_warped(128..255) | gx,gy,cnx,cny]

    // ---- head MLP ----------------------------------------------------------
    dense<260, 256>(hw0, hb0, bufA, bufB, ws);
    epi_relu(bufB, 256);
    __syncthreads();
    dense<256, 128>(hw1, hb1, bufB, bufA, ws);
    epi_relu(bufA, 128);
    __syncthreads();
    dense<128, 64>(hw2, hb2, bufA, bufB, ws);
    epi_relu(bufB, 64);
    __syncthreads();

    // ---- final 64->2 + flow assembly ---------------------------------------
    if (tid < 128) {
        const int p = tid & 63, ch = tid >> 6;
        float acc = hb3[ch];
        #pragma unroll
        for (int k = 0; k < 64; ++k)
            acc += bufB[k * LDP + p] * hw3[2 * k + ch];
        float fl = ch ? (cqyA[p] + acc * 384.f) : (cqxA[p] + acc * 512.f);
        out[(((size_t)(b * 2 + ch)) * 384 + yrow) * 512 + (xbase + p)] = fl;
    }
}

extern "C" void kernel_launch(void* const* d_in, const int* in_sizes, int n_in,
                              void* d_out, int out_size)
{
    // d_in[0] = img (unused by the reference computation)
    const float* feat_s8     = (const float*)d_in[1];
    const float* feat1_s8    = (const float*)d_in[2];
    const float* feat_s16    = (const float*)d_in[3];
    const float* ctx_s8      = (const float*)d_in[4];
    const float* coarse_flow = (const float*)d_in[5];
    const float* proj_ctx_w  = (const float*)d_in[6];
    const float* proj_ctx_b  = (const float*)d_in[7];
    const float* gate1       = (const float*)d_in[8];
    const float* ffn1_w1     = (const float*)d_in[9];
    const float* ffn1_b1     = (const float*)d_in[10];
    const float* ffn1_w2     = (const float*)d_in[11];
    const float* ffn1_b2     = (const float*)d_in[12];
    const float* proj_s8_w   = (const float*)d_in[13];
    const float* proj_s8_b   = (const float*)d_in[14];
    const float* gate2       = (const float*)d_in[15];
    const float* ffn2_w1     = (const float*)d_in[16];
    const float* ffn2_b1     = (const float*)d_in[17];
    const float* ffn2_w2     = (const float*)d_in[18];
    const float* ffn2_b2     = (const float*)d_in[19];
    const float* hw0         = (const float*)d_in[20];
    const float* hb0         = (const float*)d_in[21];
    const float* hw1         = (const float*)d_in[22];
    const float* hb1         = (const float*)d_in[23];
    const float* hw2         = (const float*)d_in[24];
    const float* hb2         = (const float*)d_in[25];
    const float* hw3         = (const float*)d_in[26];
    const float* hb3         = (const float*)d_in[27];

    const int smem_bytes = SMEM_FLOATS * 4;
    cudaFuncSetAttribute(ifd_kernel, cudaFuncAttributeMaxDynamicSharedMemorySize, smem_bytes);

    ifd_kernel<<<6144, NT, smem_bytes>>>(
        feat_s8, feat1_s8, feat_s16, ctx_s8, coarse_flow,
        proj_ctx_w, proj_ctx_b, gate1,
        ffn1_w1, ffn1_b1, ffn1_w2, ffn1_b2,
        proj_s8_w, proj_s8_b, gate2,
        ffn2_w1, ffn2_b1, ffn2_w2, ffn2_b2,
        hw0, hb0, hw1, hb1, hw2, hb2, hw3, hb3,
        (float*)d_out);
}

// round 7
// speedup vs baseline: 1.5937x; 1.5937x over previous
#include <cuda_runtime.h>
#include <math.h>

#define LDA 268         // padded per-point stride for big activation buffers
#define LDF 132         // padded per-point stride for 128-wide residual buffer
#define WCAP 8192       // weight staging buffer, floats (32KB)
#define NT 512          // threads per CTA

typedef unsigned long long ull;

// ---------------- f32x2 packed-FMA helpers ----------------------------------
__device__ __forceinline__ ull dup2(float a) {
    ull r; unsigned u = __float_as_uint(a);
    asm("mov.b64 %0, {%1, %1};" : "=l"(r) : "r"(u));
    return r;
}
__device__ __forceinline__ void ffma2(ull& d, ull a, ull b) {
    asm("fma.rn.f32x2 %0, %1, %2, %0;" : "+l"(d) : "l"(a), "l"(b));
}
__device__ __forceinline__ float2 unpk(ull v) {
    unsigned lo, hi;
    asm("mov.b64 {%0, %1}, %2;" : "=r"(lo), "=r"(hi) : "l"(v));
    return make_float2(__uint_as_float(lo), __uint_as_float(hi));
}

// ---------------- bilinear sampler setup (grid_sample semantics) ------------
__device__ __forceinline__ void make_sampler(float gx, float gy, int Ws, int Hs, int p,
                                             int* o, float* w)
{
    float xf = fmaf(gx + 1.f, 0.5f * (float)Ws, -0.5f);
    float yf = fmaf(gy + 1.f, 0.5f * (float)Hs, -0.5f);
    float x0f = floorf(xf), y0f = floorf(yf);
    int x0 = (int)x0f, y0 = (int)y0f;
    int ix0 = min(max(x0,     0), Ws - 1);
    int ix1 = min(max(x0 + 1, 0), Ws - 1);
    int iy0 = min(max(y0,     0), Hs - 1);
    int iy1 = min(max(y0 + 1, 0), Hs - 1);
    o[p]       = iy0 * Ws + ix0;
    o[64 + p]  = iy0 * Ws + ix1;
    o[128 + p] = iy1 * Ws + ix0;
    o[192 + p] = iy1 * Ws + ix1;
    w[p]      = xf - x0f;
    w[64 + p] = yf - y0f;
}

// ---- gather C channels for 64 points into smem [p][ld] at column coff ------
template<int C, int HWs>
__device__ __forceinline__ void sample_fm(const float* __restrict__ fm,
                                          const int* __restrict__ o,
                                          const float* __restrict__ w,
                                          float* __restrict__ dst, int ld, int coff)
{
    const int tid = threadIdx.x;
    for (int t = tid; t < C * 64; t += NT) {
        const int p = t & 63, c = t >> 6;
        const float* f = fm + c * HWs;
        float v00 = f[o[p]],       v01 = f[o[64 + p]];
        float v10 = f[o[128 + p]], v11 = f[o[192 + p]];
        float fx = w[p], fy = w[64 + p];
        float va = fmaf(fx, v01 - v00, v00);
        float vb = fmaf(fx, v11 - v10, v10);
        dst[p * ld + coff + c] = fmaf(fy, vb - va, va);
    }
}

// ---------------- dense layer, transposed activations -----------------------
// out[p][j] = epilogue( sum_k in[p][k] * W[k][j] + bias[j] )
// Each warp owns an 8(or 4)-wide j block (weights broadcast across lanes);
// each lane owns points (lane, lane+32). MODE: 0=bias, 1=gelu, 2=relu,
// 3=residual: out = res[p][j] + sg[j]*(acc+bias).
template<int K, int N, int MODE, bool PRE_SYNC>
__device__ __forceinline__ void dense2(const float* __restrict__ W,
                                       const float* __restrict__ bias,
                                       const float* __restrict__ inS, int ldi,
                                       float* __restrict__ outS, int ldo,
                                       float* __restrict__ ws,
                                       const float* __restrict__ resS,
                                       const float* __restrict__ sg)
{
    const int tid  = threadIdx.x;
    const int warp = tid >> 5;
    const int lane = tid & 31;
    constexpr int JW = (N >= 128) ? 8 : 4;     // j columns per warp block
    constexpr int JSTR = 16 * JW;              // j covered by all 16 warps
    constexpr int NB = (N > JSTR) ? 2 : 1;     // blocks per warp
    const int jb = warp * JW;
    constexpr int KC0 = WCAP / N;
    constexpr int KC = (KC0 < K) ? KC0 : K;

    ull acc[NB][JW / 2][2];
    #pragma unroll
    for (int b = 0; b < NB; ++b)
        #pragma unroll
        for (int jp = 0; jp < JW / 2; ++jp) { acc[b][jp][0] = 0; acc[b][jp][1] = 0; }

    for (int k0 = 0; k0 < K; k0 += KC) {
        const int kc = (K - k0 < KC) ? (K - k0) : KC;
        __syncthreads();
        {   // stage weight chunk (coalesced float4)
            const float4* src = (const float4*)(W + (size_t)k0 * N);
            float4* dst4 = (float4*)ws;
            const int n4 = (kc * N) >> 2;
            for (int i = tid; i < n4; i += NT) dst4[i] = src[i];
        }
        __syncthreads();

        const float* ip0 = inS + lane * ldi + k0;
        const float* ip1 = inS + (lane + 32) * ldi + k0;
        for (int kk = 0; kk < kc; kk += 4) {
            float4 a0 = *(const float4*)(ip0 + kk);
            float4 a1 = *(const float4*)(ip1 + kk);
            const float* wr = ws + kk * N + jb;
            #pragma unroll
            for (int r = 0; r < 4; ++r) {
                float e0 = (r == 0) ? a0.x : (r == 1) ? a0.y : (r == 2) ? a0.z : a0.w;
                float e1 = (r == 0) ? a1.x : (r == 1) ? a1.y : (r == 2) ? a1.z : a1.w;
                ull av0 = dup2(e0), av1 = dup2(e1);
                #pragma unroll
                for (int b = 0; b < NB; ++b) {
                    const ulonglong2* wp = (const ulonglong2*)(wr + r * N + b * JSTR);
                    ulonglong2 wv = wp[0];
                    ffma2(acc[b][0][0], av0, wv.x);
                    ffma2(acc[b][0][1], av1, wv.x);
                    ffma2(acc[b][1][0], av0, wv.y);
                    ffma2(acc[b][1][1], av1, wv.y);
                    if (JW == 8) {
                        ulonglong2 wv2 = wp[1];
                        ffma2(acc[b][2][0], av0, wv2.x);
                        ffma2(acc[b][2][1], av1, wv2.x);
                        ffma2(acc[b][3][0], av0, wv2.y);
                        ffma2(acc[b][3][1], av1, wv2.y);
                    }
                }
            }
        }
    }

    if (PRE_SYNC) __syncthreads();   // in-place layers: finish all reads first

    // fused epilogue + writeback
    #pragma unroll
    for (int b = 0; b < NB; ++b) {
        const int j0 = jb + b * JSTR;
        float v[2][JW];
        #pragma unroll
        for (int jp = 0; jp < JW / 2; ++jp) {
            float2 u0 = unpk(acc[b][jp][0]);
            float2 u1 = unpk(acc[b][jp][1]);
            v[0][2 * jp] = u0.x; v[0][2 * jp + 1] = u0.y;
            v[1][2 * jp] = u1.x; v[1][2 * jp + 1] = u1.y;
        }
        float rv[2][JW];
        if (MODE == 3) {
            #pragma unroll
            for (int pp = 0; pp < 2; ++pp) {
                const float* rp = resS + (lane + pp * 32) * LDF + j0;
                #pragma unroll
                for (int q = 0; q < JW / 4; ++q) {
                    float4 r4 = *(const float4*)(rp + 4 * q);
                    rv[pp][4 * q] = r4.x; rv[pp][4 * q + 1] = r4.y;
                    rv[pp][4 * q + 2] = r4.z; rv[pp][4 * q + 3] = r4.w;
                }
            }
        }
        #pragma unroll
        for (int jj = 0; jj < JW; ++jj) {
            float bb = __ldg(bias + j0 + jj);
            float sgv = (MODE == 3) ? sg[j0 + jj] : 0.f;
            #pragma unroll
            for (int pp = 0; pp < 2; ++pp) {
                float x = v[pp][jj] + bb;
                if (MODE == 1)      x = 0.5f * x * (1.f + erff(x * 0.70710678118654752f));
                else if (MODE == 2) x = fmaxf(x, 0.f);
                else if (MODE == 3) x = rv[pp][jj] + sgv * x;
                v[pp][jj] = x;
            }
        }
        #pragma unroll
        for (int pp = 0; pp < 2; ++pp) {
            float* op = outS + (lane + pp * 32) * ldo + j0;
            #pragma unroll
            for (int q = 0; q < JW / 4; ++q)
                *(float4*)(op + 4 * q) =
                    make_float4(v[pp][4 * q], v[pp][4 * q + 1],
                                v[pp][4 * q + 2], v[pp][4 * q + 3]);
        }
    }
}

// ---------------- fused kernel ----------------------------------------------
// smem floats: A[64*268] | B[64*268] | F[64*132] | ws[8192] | aux[1536]
#define SMEM_FLOATS (2 * 64 * LDA + 64 * LDF + WCAP + 1536)

__global__ __launch_bounds__(NT, 1)
void ifd_kernel(const float* __restrict__ feat_s8,
                const float* __restrict__ feat1_s8,
                const float* __restrict__ feat_s16,
                const float* __restrict__ ctx_s8,
                const float* __restrict__ coarse_flow,
                const float* __restrict__ proj_ctx_w, const float* __restrict__ proj_ctx_b,
                const float* __restrict__ gate1,
                const float* __restrict__ ffn1_w1, const float* __restrict__ ffn1_b1,
                const float* __restrict__ ffn1_w2, const float* __restrict__ ffn1_b2,
                const float* __restrict__ proj_s8_w, const float* __restrict__ proj_s8_b,
                const float* __restrict__ gate2,
                const float* __restrict__ ffn2_w1, const float* __restrict__ ffn2_b1,
                const float* __restrict__ ffn2_w2, const float* __restrict__ ffn2_b2,
                const float* __restrict__ hw0, const float* __restrict__ hb0,
                const float* __restrict__ hw1, const float* __restrict__ hb1,
                const float* __restrict__ hw2, const float* __restrict__ hb2,
                const float* __restrict__ hw3, const float* __restrict__ hb3,
                float* __restrict__ out)
{
    extern __shared__ float sm[];
    float* A  = sm;
    float* Bb = sm + 64 * LDA;
    float* F  = sm + 2 * 64 * LDA;
    float* ws = F + 64 * LDF;
    float* aux = ws + WCAP;

    int*   s8o  = (int*)aux;            // 256 ints
    float* s8w  = aux + 256;            // 128
    int*   s16o = (int*)(aux + 384);    // 256
    float* s16w = aux + 640;            // 128
    int*   wro  = (int*)(aux + 768);    // 256
    float* wrw  = aux + 1024;           // 128
    float* sg1  = aux + 1152;           // 128
    float* sg2  = aux + 1280;           // 128
    float* cqxA = aux + 1408;           // 64
    float* cqyA = aux + 1472;           // 64

    const int tid = threadIdx.x;
    const int blk = blockIdx.x;
    const int b = (blk >= 3072) ? 1 : 0;       // 3072 tiles per batch
    const int t = blk - b * 3072;
    const int yrow  = t >> 3;
    const int xbase = (t & 7) << 6;

    const float* f8b  = feat_s8     + (size_t)b * 128 * 3072;
    const float* f1b  = feat1_s8    + (size_t)b * 128 * 3072;
    const float* f16b = feat_s16    + (size_t)b * 128 * 768;
    const float* cxb  = ctx_s8      + (size_t)b * 64  * 3072;
    const float* cfb  = coarse_flow + (size_t)b * 2   * 3072;

    // ---- phase 0: per-point samplers, coarse flow, warp coords -------------
    if (tid < 64) {
        const int p = tid;
        const float lim = 1.f - 1e-6f;
        float gx = (2.f * (float)(xbase + p) + 1.f) * (1.f / 512.f) - 1.f;
        float gy = (2.f * (float)yrow + 1.f) * (1.f / 384.f) - 1.f;
        gx = fminf(fmaxf(gx, -lim), lim);
        gy = fminf(fmaxf(gy, -lim), lim);
        make_sampler(gx, gy, 64, 48, p, s8o, s8w);
        make_sampler(gx, gy, 32, 24, p, s16o, s16w);

        float fx = s8w[p], fy = s8w[64 + p];
        int o00 = s8o[p], o01 = s8o[64 + p], o10 = s8o[128 + p], o11 = s8o[192 + p];
        float c0, c1;
        {
            const float* f = cfb;
            float va = fmaf(fx, f[o01] - f[o00], f[o00]);
            float vb = fmaf(fx, f[o11] - f[o10], f[o10]);
            c0 = fmaf(fy, vb - va, va);
            f = cfb + 3072;
            va = fmaf(fx, f[o01] - f[o00], f[o00]);
            vb = fmaf(fx, f[o11] - f[o10], f[o10]);
            c1 = fmaf(fy, vb - va, va);
        }
        float cqx = 8.f * c0, cqy = 8.f * c1;      // coarse_at_q (scale = [8,8])
        cqxA[p] = cqx; cqyA[p] = cqy;
        float wxn = fminf(fmaxf(gx + cqx * (2.f / 512.f), -lim), lim);
        float wyn = fminf(fmaxf(gy + cqy * (2.f / 384.f), -lim), lim);
        make_sampler(wxn, wyn, 64, 48, p, wro, wrw);

        // mlp_in tail cols (256..259 of A; GEMMs never write those columns)
        A[p * LDA + 256] = gx;
        A[p * LDA + 257] = gy;
        A[p * LDA + 258] = cqx * (1.f / 512.f);
        A[p * LDA + 259] = cqy * (1.f / 384.f);
    }
    if (tid < 128) {
        sg1[tid] = 1.f / (1.f + expf(-gate1[tid]));
        sg2[tid] = 1.f / (1.f + expf(-gate2[tid]));
    }
    __syncthreads();

    // ---- sampling: fctx -> A[:,0..63], f8 -> F -----------------------------
    sample_fm<64, 3072>(cxb, s8o, s8w, A, LDA, 0);
    sample_fm<128, 3072>(f8b, s8o, s8w, F, LDF, 0);
    __syncthreads();

    // ---- L1: h1 = f8 + sg1 * (fctx @ Wc + b)  -> B[:,0..127] ---------------
    dense2<64, 128, 3, false>(proj_ctx_w, proj_ctx_b, A, LDA, Bb, LDA, ws, F, sg1);
    __syncthreads();

    // f16 -> F (f8 dead)
    sample_fm<128, 768>(f16b, s16o, s16w, F, LDF, 0);
    __syncthreads();

    // ---- L2: gelu(h1 @ w1 + b) -> A[:,0..255] ------------------------------
    dense2<128, 256, 1, false>(ffn1_w1, ffn1_b1, Bb, LDA, A, LDA, ws, 0, 0);
    __syncthreads();

    // ---- L3: h2 = t @ w2 + b -> B[:,0..127] --------------------------------
    dense2<256, 128, 0, false>(ffn1_w2, ffn1_b2, A, LDA, Bb, LDA, ws, 0, 0);
    __syncthreads();

    // f1_warped -> A[:,128..255] (A's t dead after L3)
    sample_fm<128, 3072>(f1b, wro, wrw, A, LDA, 128);
    __syncthreads();

    // ---- L4: h3 = f16 + sg2 * (h2 @ Wp + b) -> B[:,0..127] (in-place) ------
    dense2<128, 128, 3, true>(proj_s8_w, proj_s8_b, Bb, LDA, Bb, LDA, ws, F, sg2);
    __syncthreads();

    // ---- L5: gelu(h3 @ w1 + b) -> B[:,0..255] (in-place overlap) -----------
    dense2<128, 256, 1, true>(ffn2_w1, ffn2_b1, Bb, LDA, Bb, LDA, ws, 0, 0);
    __syncthreads();

    // ---- L6: fused = t @ w2 + b -> A[:,0..127] -----------------------------
    dense2<256, 128, 0, false>(ffn2_w2, ffn2_b2, Bb, LDA, A, LDA, ws, 0, 0);
    __syncthreads();
    // A = mlp_in: [fused | f1_warped | gx,gy,cnx,cny]

    // ---- head MLP ----------------------------------------------------------
    dense2<260, 256, 2, false>(hw0, hb0, A, LDA, Bb, LDA, ws, 0, 0);
    __syncthreads();
    dense2<256, 128, 2, false>(hw1, hb1, Bb, LDA, F, LDF, ws, 0, 0);
    __syncthreads();
    dense2<128, 64, 2, false>(hw2, hb2, F, LDF, Bb, LDA, ws, 0, 0);
    __syncthreads();

    // ---- final 64->2 + flow assembly ---------------------------------------
    if (tid < 128) {
        const int p = tid & 63, ch = tid >> 6;
        float acc = __ldg(hb3 + ch);
        const float4* row = (const float4*)(Bb + p * LDA);
        #pragma unroll
        for (int k4 = 0; k4 < 16; ++k4) {
            float4 v = row[k4];
            acc = fmaf(v.x, __ldg(hw3 + 8 * k4 + 0 + ch), acc);
            acc = fmaf(v.y, __ldg(hw3 + 8 * k4 + 2 + ch), acc);
            acc = fmaf(v.z, __ldg(hw3 + 8 * k4 + 4 + ch), acc);
            acc = fmaf(v.w, __ldg(hw3 + 8 * k4 + 6 + ch), acc);
        }
        float fl = ch ? (cqyA[p] + acc * 384.f) : (cqxA[p] + acc * 512.f);
        out[(((size_t)(b * 2 + ch)) * 384 + yrow) * 512 + (xbase + p)] = fl;
    }
}

extern "C" void kernel_launch(void* const* d_in, const int* in_sizes, int n_in,
                              void* d_out, int out_size)
{
    // d_in[0] = img (unused by the reference computation)
    const float* feat_s8     = (const float*)d_in[1];
    const float* feat1_s8    = (const float*)d_in[2];
    const float* feat_s16    = (const float*)d_in[3];
    const float* ctx_s8      = (const float*)d_in[4];
    const float* coarse_flow = (const float*)d_in[5];
    const float* proj_ctx_w  = (const float*)d_in[6];
    const float* proj_ctx_b  = (const float*)d_in[7];
    const float* gate1       = (const float*)d_in[8];
    const float* ffn1_w1     = (const float*)d_in[9];
    const float* ffn1_b1     = (const float*)d_in[10];
    const float* ffn1_w2     = (const float*)d_in[11];
    const float* ffn1_b2     = (const float*)d_in[12];
    const float* proj_s8_w   = (const float*)d_in[13];
    const float* proj_s8_b   = (const float*)d_in[14];
    const float* gate2       = (const float*)d_in[15];
    const float* ffn2_w1     = (const float*)d_in[16];
    const float* ffn2_b1     = (const float*)d_in[17];
    const float* ffn2_w2     = (const float*)d_in[18];
    const float* ffn2_b2     = (const float*)d_in[19];
    const float* hw0         = (const float*)d_in[20];
    const float* hb0         = (const float*)d_in[21];
    const float* hw1         = (const float*)d_in[22];
    const float* hb1         = (const float*)d_in[23];
    const float* hw2         = (const float*)d_in[24];
    const float* hb2         = (const float*)d_in[25];
    const float* hw3         = (const float*)d_in[26];
    const float* hb3         = (const float*)d_in[27];

    const int smem_bytes = SMEM_FLOATS * 4;
    cudaFuncSetAttribute(ifd_kernel, cudaFuncAttributeMaxDynamicSharedMemorySize, smem_bytes);

    ifd_kernel<<<6144, NT, smem_bytes>>>(
        feat_s8, feat1_s8, feat_s16, ctx_s8, coarse_flow,
        proj_ctx_w, proj_ctx_b, gate1,
        ffn1_w1, ffn1_b1, ffn1_w2, ffn1_b2,
        proj_s8_w, proj_s8_b, gate2,
        ffn2_w1, ffn2_b1, ffn2_w2, ffn2_b2,
        hw0, hb0, hw1, hb1, hw2, hb2, hw3, hb3,
        (float*)d_out);
}

// round 9
// speedup vs baseline: 1.7336x; 1.0878x over previous
#include <cuda_runtime.h>
#include <math.h>

#define LDP 68          // row stride (floats) for [dim][point] buffers; 272B, 16B-aligned
#define WCAP 8192       // weight staging buffer, floats (32KB)
#define NT 512          // threads per CTA

typedef unsigned long long ull;

// ---------------- f32x2 packed-FMA helpers ----------------------------------
__device__ __forceinline__ ull dup2(float a) {
    ull r; unsigned u = __float_as_uint(a);
    asm("mov.b64 %0, {%1, %1};" : "=l"(r) : "r"(u));
    return r;
}
__device__ __forceinline__ void ffma2(ull& d, ull a, ull b) {
    asm("fma.rn.f32x2 %0, %1, %2, %0;" : "+l"(d) : "l"(a), "l"(b));
}
__device__ __forceinline__ float2 unpk(ull v) {
    unsigned lo, hi;
    asm("mov.b64 {%0, %1}, %2;" : "=r"(lo), "=r"(hi) : "l"(v));
    return make_float2(__uint_as_float(lo), __uint_as_float(hi));
}

// ---------------- bilinear sampler setup (grid_sample semantics) ------------
__device__ __forceinline__ void make_sampler(float gx, float gy, int Ws, int Hs, int p,
                                             int* o, float* w)
{
    float xf = fmaf(gx + 1.f, 0.5f * (float)Ws, -0.5f);
    float yf = fmaf(gy + 1.f, 0.5f * (float)Hs, -0.5f);
    float x0f = floorf(xf), y0f = floorf(yf);
    int x0 = (int)x0f, y0 = (int)y0f;
    int ix0 = min(max(x0,     0), Ws - 1);
    int ix1 = min(max(x0 + 1, 0), Ws - 1);
    int iy0 = min(max(y0,     0), Hs - 1);
    int iy1 = min(max(y0 + 1, 0), Hs - 1);
    o[p]       = iy0 * Ws + ix0;
    o[64 + p]  = iy0 * Ws + ix1;
    o[128 + p] = iy1 * Ws + ix0;
    o[192 + p] = iy1 * Ws + ix1;
    w[p]      = xf - x0f;
    w[64 + p] = yf - y0f;
}

// ---- gather C channels for 64 points into smem rows dst[c*LDP + p] ---------
template<int C, int HWs>
__device__ __forceinline__ void sample_fm(const float* __restrict__ fm,
                                          const int* __restrict__ o,
                                          const float* __restrict__ w,
                                          float* __restrict__ dst)
{
    const int tid = threadIdx.x;
    for (int t = tid; t < C * 64; t += NT) {
        const int p = t & 63, c = t >> 6;
        const float* f = fm + c * HWs;
        float v00 = f[o[p]],       v01 = f[o[64 + p]];
        float v10 = f[o[128 + p]], v11 = f[o[192 + p]];
        float fx = w[p], fy = w[64 + p];
        float va = fmaf(fx, v01 - v00, v00);
        float vb = fmaf(fx, v11 - v10, v10);
        dst[c * LDP + p] = fmaf(fy, vb - va, va);
    }
}

// ---------------- dense layer, [k][p] activations, 4p x 8j thread tiles -----
// out[j][p] = epilogue( sum_k in[k][p] * W[k][j] + bias[j] )
// warp = (wr 0-3 point-row, wc 0-3 j-col); lane = (pg 0-3, jg 0-7).
// Thread owns 4 consecutive points and JT j columns (two 4-j groups for N=256).
// MODE: 0=bias, 1=gelu, 2=relu, 3=residual out = res + sg[j]*(acc+bias).
template<int K, int N, int MODE, bool PRE_SYNC>
__device__ __forceinline__ void dense3(const float* __restrict__ W,
                                       const float* __restrict__ bias,
                                       const float* __restrict__ inS,
                                       float* __restrict__ outS,
                                       float* __restrict__ ws,
                                       const float* __restrict__ resS,
                                       const float* __restrict__ sg)
{
    const int tid  = threadIdx.x;
    const int warp = tid >> 5, lane = tid & 31;
    const int wr = warp & 3, wc = warp >> 2;
    const int pg = lane & 3, jg = lane >> 2;
    const int ppos = wr * 16 + pg * 4;

    constexpr int JT = N / 32;                 // j per thread: 8,4,2
    constexpr int NG = (JT >= 4) ? JT / 4 : 1; // float4 weight groups
    constexpr int JP = (JT >= 4) ? 2 : 1;      // j-pairs per group
    constexpr int JJ = (JT >= 4) ? 4 : 2;      // j per group
    constexpr int KC0 = WCAP / N;
    constexpr int KC = (KC0 < K) ? KC0 : K;

    ull acc[NG][JP][4];
    #pragma unroll
    for (int g = 0; g < NG; ++g)
        #pragma unroll
        for (int jp = 0; jp < JP; ++jp)
            #pragma unroll
            for (int p = 0; p < 4; ++p) acc[g][jp][p] = 0;

    for (int k0 = 0; k0 < K; k0 += KC) {
        const int kc = (K - k0 < KC) ? (K - k0) : KC;
        __syncthreads();
        {   // stage weight chunk (coalesced float4)
            const float4* src = (const float4*)(W + (size_t)k0 * N);
            float4* dst4 = (float4*)ws;
            const int n4 = (kc * N) >> 2;
            for (int i = tid; i < n4; i += NT) dst4[i] = src[i];
        }
        __syncthreads();

        const float* ip = inS + (size_t)k0 * LDP + ppos;
        #pragma unroll 2
        for (int kk = 0; kk < kc; ++kk) {
            float4 a = *(const float4*)(ip + kk * LDP);
            ull ap0 = dup2(a.x), ap1 = dup2(a.y), ap2 = dup2(a.z), ap3 = dup2(a.w);
            if (JT >= 4) {
                #pragma unroll
                for (int g = 0; g < NG; ++g) {
                    const int jb = wc * (N / 4) + g * 32 + jg * 4;
                    ulonglong2 wv = *(const ulonglong2*)(ws + kk * N + jb);
                    ffma2(acc[g][0][0], wv.x, ap0);
                    ffma2(acc[g][0][1], wv.x, ap1);
                    ffma2(acc[g][0][2], wv.x, ap2);
                    ffma2(acc[g][0][3], wv.x, ap3);
                    ffma2(acc[g][1][0], wv.y, ap0);
                    ffma2(acc[g][1][1], wv.y, ap1);
                    ffma2(acc[g][1][2], wv.y, ap2);
                    ffma2(acc[g][1][3], wv.y, ap3);
                }
            } else {
                const int jb = wc * 16 + jg * 2;
                ull wv = *(const ull*)(ws + kk * N + jb);
                ffma2(acc[0][0][0], wv, ap0);
                ffma2(acc[0][0][1], wv, ap1);
                ffma2(acc[0][0][2], wv, ap2);
                ffma2(acc[0][0][3], wv, ap3);
            }
        }
    }

    if (PRE_SYNC) __syncthreads();   // in-place layers: finish all reads first

    // fused epilogue + writeback
    #pragma unroll
    for (int g = 0; g < NG; ++g) {
        const int jb = (JT >= 4) ? (wc * (N / 4) + g * 32 + jg * 4)
                                 : (wc * 16 + jg * 2);
        float v[JJ][4];
        #pragma unroll
        for (int jp = 0; jp < JP; ++jp)
            #pragma unroll
            for (int p = 0; p < 4; ++p) {
                float2 u = unpk(acc[g][jp][p]);
                v[2 * jp][p]     = u.x;
                v[2 * jp + 1][p] = u.y;
            }
        #pragma unroll
        for (int jj = 0; jj < JJ; ++jj) {
            const int j = jb + jj;
            const float bb = __ldg(bias + j);
            float x0 = v[jj][0] + bb, x1 = v[jj][1] + bb;
            float x2 = v[jj][2] + bb, x3 = v[jj][3] + bb;
            if (MODE == 1) {
                x0 = 0.5f * x0 * (1.f + erff(x0 * 0.70710678118654752f));
                x1 = 0.5f * x1 * (1.f + erff(x1 * 0.70710678118654752f));
                x2 = 0.5f * x2 * (1.f + erff(x2 * 0.70710678118654752f));
                x3 = 0.5f * x3 * (1.f + erff(x3 * 0.70710678118654752f));
            } else if (MODE == 2) {
                x0 = fmaxf(x0, 0.f); x1 = fmaxf(x1, 0.f);
                x2 = fmaxf(x2, 0.f); x3 = fmaxf(x3, 0.f);
            } else if (MODE == 3) {
                const float sgv = sg[j];
                float4 r4 = *(const float4*)(resS + (size_t)j * LDP + ppos);
                x0 = r4.x + sgv * x0; x1 = r4.y + sgv * x1;
                x2 = r4.z + sgv * x2; x3 = r4.w + sgv * x3;
            }
            *(float4*)(outS + (size_t)j * LDP + ppos) = make_float4(x0, x1, x2, x3);
        }
    }
}

// ---------------- fused kernel ----------------------------------------------
// smem floats: A[260*68] | B[260*68] | F[128*68] | ws[8192] | aux[1536]
#define SMEM_FLOATS (2 * 260 * LDP + 128 * LDP + WCAP + 1536)

__global__ __launch_bounds__(NT, 1)
void ifd_kernel(const float* __restrict__ feat_s8,
                const float* __restrict__ feat1_s8,
                const float* __restrict__ feat_s16,
                const float* __restrict__ ctx_s8,
                const float* __restrict__ coarse_flow,
                const float* __restrict__ proj_ctx_w, const float* __restrict__ proj_ctx_b,
                const float* __restrict__ gate1,
                const float* __restrict__ ffn1_w1, const float* __restrict__ ffn1_b1,
                const float* __restrict__ ffn1_w2, const float* __restrict__ ffn1_b2,
                const float* __restrict__ proj_s8_w, const float* __restrict__ proj_s8_b,
                const float* __restrict__ gate2,
                const float* __restrict__ ffn2_w1, const float* __restrict__ ffn2_b1,
                const float* __restrict__ ffn2_w2, const float* __restrict__ ffn2_b2,
                const float* __restrict__ hw0, const float* __restrict__ hb0,
                const float* __restrict__ hw1, const float* __restrict__ hb1,
                const float* __restrict__ hw2, const float* __restrict__ hb2,
                const float* __restrict__ hw3, const float* __restrict__ hb3,
                float* __restrict__ out)
{
    extern __shared__ float sm[];
    float* A  = sm;
    float* Bb = sm + 260 * LDP;
    float* F  = sm + 2 * 260 * LDP;
    float* ws = F + 128 * LDP;
    float* aux = ws + WCAP;

    int*   s8o  = (int*)aux;            // 256 ints
    float* s8w  = aux + 256;            // 128
    int*   s16o = (int*)(aux + 384);    // 256
    float* s16w = aux + 640;            // 128
    int*   wro  = (int*)(aux + 768);    // 256
    float* wrw  = aux + 1024;           // 128
    float* sg1  = aux + 1152;           // 128
    float* sg2  = aux + 1280;           // 128
    float* cqxA = aux + 1408;           // 64
    float* cqyA = aux + 1472;           // 64

    const int tid = threadIdx.x;
    const int blk = blockIdx.x;
    const int b = (blk >= 3072) ? 1 : 0;       // 3072 tiles per batch
    const int t = blk - b * 3072;
    const int yrow  = t >> 3;
    const int xbase = (t & 7) << 6;

    const float* f8b  = feat_s8     + (size_t)b * 128 * 3072;
    const float* f1b  = feat1_s8    + (size_t)b * 128 * 3072;
    const float* f16b = feat_s16    + (size_t)b * 128 * 768;
    const float* cxb  = ctx_s8      + (size_t)b * 64  * 3072;
    const float* cfb  = coarse_flow + (size_t)b * 2   * 3072;

    // ---- phase 0: per-point samplers, coarse flow, warp coords -------------
    if (tid < 64) {
        const int p = tid;
        const float lim = 1.f - 1e-6f;
        float gx = (2.f * (float)(xbase + p) + 1.f) * (1.f / 512.f) - 1.f;
        float gy = (2.f * (float)yrow + 1.f) * (1.f / 384.f) - 1.f;
        gx = fminf(fmaxf(gx, -lim), lim);
        gy = fminf(fmaxf(gy, -lim), lim);
        make_sampler(gx, gy, 64, 48, p, s8o, s8w);
        make_sampler(gx, gy, 32, 24, p, s16o, s16w);

        float fx = s8w[p], fy = s8w[64 + p];
        int o00 = s8o[p], o01 = s8o[64 + p], o10 = s8o[128 + p], o11 = s8o[192 + p];
        float c0, c1;
        {
            const float* f = cfb;
            float va = fmaf(fx, f[o01] - f[o00], f[o00]);
            float vb = fmaf(fx, f[o11] - f[o10], f[o10]);
            c0 = fmaf(fy, vb - va, va);
            f = cfb + 3072;
            va = fmaf(fx, f[o01] - f[o00], f[o00]);
            vb = fmaf(fx, f[o11] - f[o10], f[o10]);
            c1 = fmaf(fy, vb - va, va);
        }
        float cqx = 8.f * c0, cqy = 8.f * c1;      // coarse_at_q (scale = [8,8])
        cqxA[p] = cqx; cqyA[p] = cqy;
        float wxn = fminf(fmaxf(gx + cqx * (2.f / 512.f), -lim), lim);
        float wyn = fminf(fmaxf(gy + cqy * (2.f / 384.f), -lim), lim);
        make_sampler(wxn, wyn, 64, 48, p, wro, wrw);

        // mlp_in tail rows (256..259; GEMMs never write those rows of A)
        A[256 * LDP + p] = gx;
        A[257 * LDP + p] = gy;
        A[258 * LDP + p] = cqx * (1.f / 512.f);
        A[259 * LDP + p] = cqy * (1.f / 384.f);
    }
    if (tid < 128) {
        sg1[tid] = 1.f / (1.f + expf(-gate1[tid]));
        sg2[tid] = 1.f / (1.f + expf(-gate2[tid]));
    }
    __syncthreads();

    // ---- sampling: fctx -> A rows 0..63, f8 -> F ---------------------------
    sample_fm<64, 3072>(cxb, s8o, s8w, A);
    sample_fm<128, 3072>(f8b, s8o, s8w, F);
    __syncthreads();

    // ---- L1: h1 = f8 + sg1 * (fctx @ Wc + b)  -> B rows 0..127 -------------
    dense3<64, 128, 3, false>(proj_ctx_w, proj_ctx_b, A, Bb, ws, F, sg1);
    __syncthreads();

    // f16 -> F (f8 dead)
    sample_fm<128, 768>(f16b, s16o, s16w, F);
    __syncthreads();

    // ---- L2: gelu(h1 @ w1 + b) -> A rows 0..255 ----------------------------
    dense3<128, 256, 1, false>(ffn1_w1, ffn1_b1, Bb, A, ws, 0, 0);
    __syncthreads();

    // ---- L3: h2 = t @ w2 + b -> B rows 0..127 ------------------------------
    dense3<256, 128, 0, false>(ffn1_w2, ffn1_b2, A, Bb, ws, 0, 0);
    __syncthreads();

    // f1_warped -> A rows 128..255 (A's t dead after L3)
    sample_fm<128, 3072>(f1b, wro, wrw, A + 128 * LDP);
    __syncthreads();

    // ---- L4: h3 = f16 + sg2 * (h2 @ Wp + b) -> B rows 0..127 (in-place) ----
    dense3<128, 128, 3, true>(proj_s8_w, proj_s8_b, Bb, Bb, ws, F, sg2);
    __syncthreads();

    // ---- L5: gelu(h3 @ w1 + b) -> B rows 0..255 (in-place overlap) ---------
    dense3<128, 256, 1, true>(ffn2_w1, ffn2_b1, Bb, Bb, ws, 0, 0);
    __syncthreads();

    // ---- L6: fused = t @ w2 + b -> A rows 0..127 ---------------------------
    dense3<256, 128, 0, false>(ffn2_w2, ffn2_b2, Bb, A, ws, 0, 0);
    __syncthreads();
    // A = mlp_in: rows [fused 0..127 | f1_warped 128..255 | gx,gy,cnx,cny]

    // ---- head MLP ----------------------------------------------------------
    dense3<260, 256, 2, false>(hw0, hb0, A, Bb, ws, 0, 0);
    __syncthreads();
    dense3<256, 128, 2, false>(hw1, hb1, Bb, F, ws, 0, 0);
    __syncthreads();
    dense3<128, 64, 2, false>(hw2, hb2, F, Bb, ws, 0, 0);
    __syncthreads();

    // ---- final 64->2 + flow assembly ---------------------------------------
    if (tid < 128) {
        const int p = tid & 63, ch = tid >> 6;
        float acc = __ldg(hb3 + ch);
        #pragma unroll
        for (int k = 0; k < 64; ++k)
            acc = fmaf(Bb[k * LDP + p], __ldg(hw3 + 2 * k + ch), acc);
        float fl = ch ? (cqyA[p] + acc * 384.f) : (cqxA[p] + acc * 512.f);
        out[(((size_t)(b * 2 + ch)) * 384 + yrow) * 512 + (xbase + p)] = fl;
    }
}

extern "C" void kernel_launch(void* const* d_in, const int* in_sizes, int n_in,
                              void* d_out, int out_size)
{
    // d_in[0] = img (unused by the reference computation)
    const float* feat_s8     = (const float*)d_in[1];
    const float* feat1_s8    = (const float*)d_in[2];
    const float* feat_s16    = (const float*)d_in[3];
    const float* ctx_s8      = (const float*)d_in[4];
    const float* coarse_flow = (const float*)d_in[5];
    const float* proj_ctx_w  = (const float*)d_in[6];
    const float* proj_ctx_b  = (const float*)d_in[7];
    const float* gate1       = (const float*)d_in[8];
    const float* ffn1_w1     = (const float*)d_in[9];
    const float* ffn1_b1     = (const float*)d_in[10];
    const float* ffn1_w2     = (const float*)d_in[11];
    const float* ffn1_b2     = (const float*)d_in[12];
    const float* proj_s8_w   = (const float*)d_in[13];
    const float* proj_s8_b   = (const float*)d_in[14];
    const float* gate2       = (const float*)d_in[15];
    const float* ffn2_w1     = (const float*)d_in[16];
    const float* ffn2_b1     = (const float*)d_in[17];
    const float* ffn2_w2     = (const float*)d_in[18];
    const float* ffn2_b2     = (const float*)d_in[19];
    const float* hw0         = (const float*)d_in[20];
    const float* hb0         = (const float*)d_in[21];
    const float* hw1         = (const float*)d_in[22];
    const float* hb1         = (const float*)d_in[23];
    const float* hw2         = (const float*)d_in[24];
    const float* hb2         = (const float*)d_in[25];
    const float* hw3         = (const float*)d_in[26];
    const float* hb3         = (const float*)d_in[27];

    const int smem_bytes = SMEM_FLOATS * 4;
    cudaFuncSetAttribute(ifd_kernel, cudaFuncAttributeMaxDynamicSharedMemorySize, smem_bytes);

    ifd_kernel<<<6144, NT, smem_bytes>>>(
        feat_s8, feat1_s8, feat_s16, ctx_s8, coarse_flow,
        proj_ctx_w, proj_ctx_b, gate1,
        ffn1_w1, ffn1_b1, ffn1_w2, ffn1_b2,
        proj_s8_w, proj_s8_b, gate2,
        ffn2_w1, ffn2_b1, ffn2_w2, ffn2_b2,
        hw0, hb0, hw1, hb1, hw2, hb2, hw3, hb3,
        (float*)d_out);
}

// round 15
// speedup vs baseline: 1.8263x; 1.0535x over previous
#include <cuda_runtime.h>
#include <cuda_bf16.h>
#include <math.h>

typedef unsigned int u32;
typedef unsigned short u16;

#define NTH 256
#define SA 296                      // A row stride (bf16 elements)
#define OFF_A0H 0
#define OFF_A0L 37888
#define OFF_A1H 75776
#define OFF_A1L 113664
#define OFF_BS  151552              // staged B: hi [N][40], lo [N][40]
#define OFF_F   192512              // fp32 residual buffer [64][132]
#define FST 132
#define OFF_AUX 226304
#define SM_TOTAL 231424

__device__ __align__(16) unsigned char g_wsc[1081344];

// ---------------- helpers ---------------------------------------------------
__device__ __forceinline__ u32 s2u(const void* p) {
    u32 a;
    asm("{ .reg .u64 t; cvta.to.shared.u64 t, %1; cvt.u32.u64 %0, t; }" : "=r"(a) : "l"(p));
    return a;
}
__device__ __forceinline__ void split_bf(float y, u16& h, u16& l) {
    __nv_bfloat16 hb = __float2bfloat16_rn(y);
    h = __bfloat16_as_ushort(hb);
    l = __bfloat16_as_ushort(__float2bfloat16_rn(y - __bfloat162float(hb)));
}
__device__ __forceinline__ float bil(const float* f, int o00, int o01, int o10, int o11,
                                     float fx, float fy) {
    float va = fmaf(fx, f[o01] - f[o00], f[o00]);
    float vb = fmaf(fx, f[o11] - f[o10], f[o10]);
    return fmaf(fy, vb - va, va);
}
__device__ __forceinline__ void mk64(float gx, float gy, int Ws, int Hs, int p,
                                     int* o, float* w) {
    float xf = fmaf(gx + 1.f, 0.5f * (float)Ws, -0.5f);
    float yf = fmaf(gy + 1.f, 0.5f * (float)Hs, -0.5f);
    float x0f = floorf(xf), y0f = floorf(yf);
    int x0 = (int)x0f, y0 = (int)y0f;
    int ix0 = min(max(x0, 0), Ws - 1), ix1 = min(max(x0 + 1, 0), Ws - 1);
    int iy0 = min(max(y0, 0), Hs - 1), iy1 = min(max(y0 + 1, 0), Hs - 1);
    o[p] = iy0 * Ws + ix0;       o[64 + p] = iy0 * Ws + ix1;
    o[128 + p] = iy1 * Ws + ix0; o[192 + p] = iy1 * Ws + ix1;
    w[p] = xf - x0f;  w[64 + p] = yf - y0f;
}
__device__ __forceinline__ void ldm4(u32* r, u32 a) {
    asm volatile("ldmatrix.sync.aligned.m8n8.x4.shared.b16 {%0,%1,%2,%3}, [%4];"
                 : "=r"(r[0]), "=r"(r[1]), "=r"(r[2]), "=r"(r[3]) : "r"(a));
}
__device__ __forceinline__ void ldm2(u32* r, u32 a) {
    asm volatile("ldmatrix.sync.aligned.m8n8.x2.shared.b16 {%0,%1}, [%2];"
                 : "=r"(r[0]), "=r"(r[1]) : "r"(a));
}
__device__ __forceinline__ void mma(float* d, const u32* a, const u32* b) {
    asm volatile("mma.sync.aligned.m16n8k16.row.col.f32.bf16.bf16.f32 "
                 "{%0,%1,%2,%3}, {%4,%5,%6,%7}, {%8,%9}, {%0,%1,%2,%3};"
                 : "+f"(d[0]), "+f"(d[1]), "+f"(d[2]), "+f"(d[3])
                 : "r"(a[0]), "r"(a[1]), "r"(a[2]), "r"(a[3]), "r"(b[0]), "r"(b[1]));
}

// ---------------- prep: W[k][n] -> chunk-major [c][n][32] bf16 hi/lo --------
__global__ void prep_kernel(const float* w0, const float* w1, const float* w2,
                            const float* w3, const float* w4, const float* w5,
                            const float* w6, const float* w7, const float* w8)
{
    const int L = blockIdx.x;
    const float* W; int K, KP, N; u32 off;
    switch (L) {
        case 0: W = w0; K = 64;  KP = 64;  N = 128; off = 0;       break;
        case 1: W = w1; K = 128; KP = 128; N = 256; off = 32768;   break;
        case 2: W = w2; K = 256; KP = 256; N = 128; off = 163840;  break;
        case 3: W = w3; K = 128; KP = 128; N = 128; off = 294912;  break;
        case 4: W = w4; K = 128; KP = 128; N = 256; off = 360448;  break;
        case 5: W = w5; K = 256; KP = 256; N = 128; off = 491520;  break;
        case 6: W = w6; K = 260; KP = 288; N = 256; off = 622592;  break;
        case 7: W = w7; K = 256; KP = 256; N = 128; off = 917504;  break;
        default:W = w8; K = 128; KP = 128; N = 64;  off = 1048576; break;
    }
    for (int idx = threadIdx.x; idx < KP * N; idx += blockDim.x) {
        int k = idx / N, n = idx % N;
        float w = (k < K) ? W[(size_t)k * N + n] : 0.f;
        u16 h, l; split_bf(w, h, l);
        int c = k >> 5, kk = k & 31;
        size_t base = (size_t)off + (size_t)c * ((size_t)N * 128);
        *(u16*)(g_wsc + base + (size_t)(n * 32 + kk) * 2) = h;
        *(u16*)(g_wsc + base + (size_t)N * 64 + (size_t)(n * 32 + kk) * 2) = l;
    }
}

// ---------------- one dense layer on mma.sync -------------------------------
// MODE: 0 bias, 1 gelu, 2 relu, 3 residual(F)+sigmoid(gate)
template<int KP, int N, int MODE>
__device__ __forceinline__ void run_layer(char* smc, u32 sb,
    const unsigned char* gW, u32 aih, u32 ail, u32 aoh, u32 aol,
    const float* __restrict__ bias, const float* __restrict__ gate)
{
    const int tid = threadIdx.x, w = tid >> 5, lane = tid & 31;
    const int mi = w & 1, ni = w >> 1;          // 2 m-blocks x 4 n-quarters
    constexpr int NQ = N / 4;
    constexpr int NT4 = NQ / 8;                 // 8 / 4 / 2
    constexpr int CH = KP / 32;

    float acc[2][NT4][4];
    #pragma unroll
    for (int mt = 0; mt < 2; ++mt)
        #pragma unroll
        for (int nt = 0; nt < NT4; ++nt)
            #pragma unroll
            for (int q = 0; q < 4; ++q) acc[mt][nt][q] = 0.f;

    // lane->ldmatrix address components
    const int arow = (lane & 7) + ((lane >> 3) & 1) * 8;
    const int akol = (lane >> 4) * 8;
    const int bl = lane & 15;
    const int brow = bl & 7, bkol = (bl >> 3) * 8;

    for (int c = 0; c < CH; ++c) {
        __syncthreads();
        {   // stage chunk c (hi+lo) with 40-element row padding
            const u32* src = (const u32*)(gW + (size_t)c * ((size_t)N * 128));
            for (int i = tid; i < N * 32; i += NTH) {
                int plane = (i >= N * 16) ? 1 : 0;
                int j = i - plane * (N * 16);
                int n = j >> 4, col = j & 15;
                *(u32*)(smc + OFF_BS + plane * (N * 80) + n * 80 + col * 4) = src[i];
            }
        }
        __syncthreads();

        #pragma unroll
        for (int kt = 0; kt < 2; ++kt) {
            u32 ahi[2][4], alo[2][4];
            #pragma unroll
            for (int mt = 0; mt < 2; ++mt) {
                u32 aoff = (u32)(((mi * 32 + mt * 16 + arow) * SA + c * 32 + kt * 16 + akol) * 2);
                ldm4(ahi[mt], sb + aih + aoff);
                ldm4(alo[mt], sb + ail + aoff);
            }
            #pragma unroll
            for (int nt = 0; nt < NT4; ++nt) {
                u32 boff = (u32)(((ni * NQ + nt * 8 + brow) * 40 + kt * 16 + bkol) * 2);
                u32 bhi[2], blo[2];
                ldm2(bhi, sb + OFF_BS + boff);
                ldm2(blo, sb + OFF_BS + (u32)(N * 80) + boff);
                #pragma unroll
                for (int mt = 0; mt < 2; ++mt) {
                    mma(acc[mt][nt], ahi[mt], bhi);
                    mma(acc[mt][nt], alo[mt], bhi);
                    mma(acc[mt][nt], ahi[mt], blo);
                }
            }
        }
    }

    // epilogue straight from registers
    const int colg = (lane & 3) * 2, rowg = lane >> 2;
    #pragma unroll
    for (int mt = 0; mt < 2; ++mt) {
        #pragma unroll
        for (int nt = 0; nt < NT4; ++nt) {
            const int n0 = ni * NQ + nt * 8 + colg;
            const float b0 = __ldg(bias + n0), b1 = __ldg(bias + n0 + 1);
            float s0 = 0.f, s1 = 0.f;
            if (MODE == 3) {
                s0 = 1.f / (1.f + expf(-__ldg(gate + n0)));
                s1 = 1.f / (1.f + expf(-__ldg(gate + n0 + 1)));
            }
            #pragma unroll
            for (int h = 0; h < 2; ++h) {
                const int r = mi * 32 + mt * 16 + rowg + h * 8;
                float v0 = acc[mt][nt][2 * h]     + b0;
                float v1 = acc[mt][nt][2 * h + 1] + b1;
                if (MODE == 1) {
                    v0 = 0.5f * v0 * (1.f + erff(v0 * 0.70710678118654752f));
                    v1 = 0.5f * v1 * (1.f + erff(v1 * 0.70710678118654752f));
                } else if (MODE == 2) {
                    v0 = fmaxf(v0, 0.f); v1 = fmaxf(v1, 0.f);
                } else if (MODE == 3) {
                    float2 rr = *(const float2*)((const float*)(smc + OFF_F) + r * FST + n0);
                    v0 = rr.x + s0 * v0; v1 = rr.y + s1 * v1;
                }
                u16 h0, l0, h1, l1;
                split_bf(v0, h0, l0); split_bf(v1, h1, l1);
                *(u32*)(smc + aoh + (r * SA + n0) * 2) = (u32)h0 | ((u32)h1 << 16);
                *(u32*)(smc + aol + (r * SA + n0) * 2) = (u32)l0 | ((u32)l1 << 16);
            }
        }
    }
}

// ---- sampling writers ------------------------------------------------------
template<int C, int HWs>
__device__ __forceinline__ void samp_split(const float* __restrict__ fm,
                                           const int* o, const float* w,
                                           char* smc, u32 dh, u32 dl, int coff)
{
    for (int t = threadIdx.x; t < C * 64; t += NTH) {
        int p = t & 63, c = t >> 6;
        float v = bil(fm + (size_t)c * HWs, o[p], o[64 + p], o[128 + p], o[192 + p],
                      w[p], w[64 + p]);
        u16 h, l; split_bf(v, h, l);
        *(u16*)(smc + dh + (p * SA + coff + c) * 2) = h;
        *(u16*)(smc + dl + (p * SA + coff + c) * 2) = l;
    }
}
template<int C, int HWs>
__device__ __forceinline__ void samp_f32(const float* __restrict__ fm,
                                         const int* o, const float* w, float* F)
{
    for (int t = threadIdx.x; t < C * 64; t += NTH) {
        int p = t & 63, c = t >> 6;
        F[p * FST + c] = bil(fm + (size_t)c * HWs, o[p], o[64 + p], o[128 + p], o[192 + p],
                             w[p], w[64 + p]);
    }
}

// ---------------- main kernel -----------------------------------------------
__global__ __launch_bounds__(NTH, 1)
void ifd_kernel(const float* __restrict__ feat_s8,  const float* __restrict__ feat1_s8,
                const float* __restrict__ feat_s16, const float* __restrict__ ctx_s8,
                const float* __restrict__ coarse_flow,
                const float* __restrict__ pcb,  const float* __restrict__ gate1,
                const float* __restrict__ f1b1, const float* __restrict__ f1b2,
                const float* __restrict__ psb,  const float* __restrict__ gate2,
                const float* __restrict__ f2b1, const float* __restrict__ f2b2,
                const float* __restrict__ hb0,  const float* __restrict__ hb1,
                const float* __restrict__ hb2,  const float* __restrict__ hw3,
                const float* __restrict__ hb3,  float* __restrict__ out)
{
    extern __shared__ char smc[];
    const u32 sb = s2u(smc);
    const int tid = threadIdx.x;

    int*   s8o  = (int*)(smc + OFF_AUX);
    float* s8w  = (float*)(smc + OFF_AUX + 1024);
    int*   s16o = (int*)(smc + OFF_AUX + 1536);
    float* s16w = (float*)(smc + OFF_AUX + 2560);
    int*   wro  = (int*)(smc + OFF_AUX + 3072);
    float* wrw  = (float*)(smc + OFF_AUX + 4096);
    float* cqx  = (float*)(smc + OFF_AUX + 4608);
    float* cqy  = (float*)(smc + OFF_AUX + 4864);
    float* F    = (float*)(smc + OFF_F);

    const int blk = blockIdx.x;
    const int b = (blk >= 3072) ? 1 : 0;
    const int t = blk - b * 3072;
    const int yrow = t >> 3, xbase = (t & 7) << 6;

    const float* f8b  = feat_s8     + (size_t)b * 128 * 3072;
    const float* f1bp = feat1_s8    + (size_t)b * 128 * 3072;
    const float* f16b = feat_s16    + (size_t)b * 128 * 768;
    const float* cxb  = ctx_s8      + (size_t)b * 64 * 3072;
    const float* cfb  = coarse_flow + (size_t)b * 2 * 3072;

    // ---- phase 0 -----------------------------------------------------------
    if (tid < 64) {
        const int p = tid;
        const float lim = 1.f - 1e-6f;
        float gx = (2.f * (float)(xbase + p) + 1.f) * (1.f / 512.f) - 1.f;
        float gy = (2.f * (float)yrow + 1.f) * (1.f / 384.f) - 1.f;
        gx = fminf(fmaxf(gx, -lim), lim);
        gy = fminf(fmaxf(gy, -lim), lim);
        mk64(gx, gy, 64, 48, p, s8o, s8w);
        mk64(gx, gy, 32, 24, p, s16o, s16w);
        float fx = s8w[p], fy = s8w[64 + p];
        int o00 = s8o[p], o01 = s8o[64 + p], o10 = s8o[128 + p], o11 = s8o[192 + p];
        float c0 = bil(cfb, o00, o01, o10, o11, fx, fy);
        float c1 = bil(cfb + 3072, o00, o01, o10, o11, fx, fy);
        float qx = 8.f * c0, qy = 8.f * c1;
        cqx[p] = qx; cqy[p] = qy;
        float wx = fminf(fmaxf(gx + qx * (2.f / 512.f), -lim), lim);
        float wy = fminf(fmaxf(gy + qy * (2.f / 384.f), -lim), lim);
        mk64(wx, wy, 64, 48, p, wro, wrw);
        // tail cols 256..259 of A0, zeros 260..287 (both planes)
        float tv[4] = { gx, gy, qx * (1.f / 512.f), qy * (1.f / 384.f) };
        #pragma unroll
        for (int v = 0; v < 4; ++v) {
            u16 h, l; split_bf(tv[v], h, l);
            *(u16*)(smc + OFF_A0H + (p * SA + 256 + v) * 2) = h;
            *(u16*)(smc + OFF_A0L + (p * SA + 256 + v) * 2) = l;
        }
        for (int c = 260; c < 288; c += 2) {
            *(u32*)(smc + OFF_A0H + (p * SA + c) * 2) = 0;
            *(u32*)(smc + OFF_A0L + (p * SA + c) * 2) = 0;
        }
    }
    __syncthreads();

    samp_split<64, 3072>(cxb, s8o, s8w, smc, OFF_A0H, OFF_A0L, 0);  // fctx -> A0
    samp_f32<128, 3072>(f8b, s8o, s8w, F);                           // f8 -> F
    __syncthreads();

    run_layer< 64, 128, 3>(smc, sb, g_wsc + 0,      OFF_A0H, OFF_A0L, OFF_A1H, OFF_A1L, pcb,  gate1);
    __syncthreads();
    samp_f32<128, 768>(f16b, s16o, s16w, F);                         // f16 -> F
    run_layer<128, 256, 1>(smc, sb, g_wsc + 32768,  OFF_A1H, OFF_A1L, OFF_A0H, OFF_A0L, f1b1, 0);
    run_layer<256, 128, 0>(smc, sb, g_wsc + 163840, OFF_A0H, OFF_A0L, OFF_A1H, OFF_A1L, f1b2, 0);
    __syncthreads();
    samp_split<128, 3072>(f1bp, wro, wrw, smc, OFF_A0H, OFF_A0L, 128); // f1w -> A0[128..255]
    run_layer<128, 128, 3>(smc, sb, g_wsc + 294912, OFF_A1H, OFF_A1L, OFF_A0H, OFF_A0L, psb,  gate2);
    run_layer<128, 256, 1>(smc, sb, g_wsc + 360448, OFF_A0H, OFF_A0L, OFF_A1H, OFF_A1L, f2b1, 0);
    run_layer<256, 128, 0>(smc, sb, g_wsc + 491520, OFF_A1H, OFF_A1L, OFF_A0H, OFF_A0L, f2b2, 0);
    // A0 = [fused | f1w | tail | zeros]
    run_layer<288, 256, 2>(smc, sb, g_wsc + 622592, OFF_A0H, OFF_A0L, OFF_A1H, OFF_A1L, hb0, 0);
    run_layer<256, 128, 2>(smc, sb, g_wsc + 917504, OFF_A1H, OFF_A1L, OFF_A0H, OFF_A0L, hb1, 0);
    run_layer<128,  64, 2>(smc, sb, g_wsc + 1048576, OFF_A0H, OFF_A0L, OFF_A1H, OFF_A1L, hb2, 0);
    __syncthreads();

    // ---- final 64->2 + flow assembly (h in A1 cols 0..63) ------------------
    if (tid < 128) {
        const int p = tid & 63, ch = tid >> 6;
        float acc = __ldg(hb3 + ch);
        #pragma unroll
        for (int k2 = 0; k2 < 32; ++k2) {
            u32 H = *(const u32*)(smc + OFF_A1H + (p * SA + 2 * k2) * 2);
            u32 L = *(const u32*)(smc + OFF_A1L + (p * SA + 2 * k2) * 2);
            float x0 = __bfloat162float(__ushort_as_bfloat16((u16)(H & 0xffff)))
                     + __bfloat162float(__ushort_as_bfloat16((u16)(L & 0xffff)));
            float x1 = __bfloat162float(__ushort_as_bfloat16((u16)(H >> 16)))
                     + __bfloat162float(__ushort_as_bfloat16((u16)(L >> 16)));
            acc = fmaf(x0, __ldg(hw3 + 4 * k2 + ch), acc);
            acc = fmaf(x1, __ldg(hw3 + 4 * k2 + 2 + ch), acc);
        }
        float fl = ch ? (cqy[p] + acc * 384.f) : (cqx[p] + acc * 512.f);
        out[(((size_t)(b * 2 + ch)) * 384 + yrow) * 512 + (xbase + p)] = fl;
    }
}

extern "C" void kernel_launch(void* const* d_in, const int* in_sizes, int n_in,
                              void* d_out, int out_size)
{
    const float* feat_s8     = (const float*)d_in[1];
    const float* feat1_s8    = (const float*)d_in[2];
    const float* feat_s16    = (const float*)d_in[3];
    const float* ctx_s8      = (const float*)d_in[4];
    const float* coarse_flow = (const float*)d_in[5];
    const float* proj_ctx_w  = (const float*)d_in[6];
    const float* proj_ctx_b  = (const float*)d_in[7];
    const float* gate1       = (const float*)d_in[8];
    const float* ffn1_w1     = (const float*)d_in[9];
    const float* ffn1_b1     = (const float*)d_in[10];
    const float* ffn1_w2     = (const float*)d_in[11];
    const float* ffn1_b2     = (const float*)d_in[12];
    const float* proj_s8_w   = (const float*)d_in[13];
    const float* proj_s8_b   = (const float*)d_in[14];
    const float* gate2       = (const float*)d_in[15];
    const float* ffn2_w1     = (const float*)d_in[16];
    const float* ffn2_b1     = (const float*)d_in[17];
    const float* ffn2_w2     = (const float*)d_in[18];
    const float* ffn2_b2     = (const float*)d_in[19];
    const float* hw0 = (const float*)d_in[20];
    const float* hb0 = (const float*)d_in[21];
    const float* hw1 = (const float*)d_in[22];
    const float* hb1 = (const float*)d_in[23];
    const float* hw2 = (const float*)d_in[24];
    const float* hb2 = (const float*)d_in[25];
    const float* hw3 = (const float*)d_in[26];
    const float* hb3 = (const float*)d_in[27];

    prep_kernel<<<9, 256>>>(proj_ctx_w, ffn1_w1, ffn1_w2, proj_s8_w, ffn2_w1,
                            ffn2_w2, hw0, hw1, hw2);

    cudaFuncSetAttribute(ifd_kernel, cudaFuncAttributeMaxDynamicSharedMemorySize, SM_TOTAL);
    ifd_kernel<<<6144, NTH, SM_TOTAL>>>(
        feat_s8, feat1_s8, feat_s16, ctx_s8, coarse_flow,
        proj_ctx_b, gate1, ffn1_b1, ffn1_b2, proj_s8_b, gate2,
        ffn2_b1, ffn2_b2, hb0, hb1, hb2, hw3, hb3, (float*)d_out);
}

// round 16
// speedup vs baseline: 2.6442x; 1.4479x over previous
#include <cuda_runtime.h>
#include <cuda_bf16.h>
#include <math.h>

typedef unsigned int u32;
typedef unsigned short u16;

#define NTH 256
#define SA 296                      // A row stride (bf16 elements)
#define OFF_A0H 0
#define OFF_A0L 37888
#define OFF_A1H 75776
#define OFF_A1L 113664
#define OFF_B0  151552              // two 16KB B staging buffers
#define BUFSZ   16384
#define OFF_F   184320              // fp32 residual buffer [64][132]
#define FST 132
#define OFF_AUX 218112
#define SM_TOTAL 223232

__device__ __align__(16) unsigned char g_wsc[1081344];

// ---------------- helpers ---------------------------------------------------
__device__ __forceinline__ u32 swz(u32 o) { return o ^ ((o >> 3) & 0x70); }
__device__ __forceinline__ u32 s2u(const void* p) {
    u32 a;
    asm("{ .reg .u64 t; cvta.to.shared.u64 t, %1; cvt.u32.u64 %0, t; }" : "=r"(a) : "l"(p));
    return a;
}
__device__ __forceinline__ void split_bf(float y, u16& h, u16& l) {
    __nv_bfloat16 hb = __float2bfloat16_rn(y);
    h = __bfloat16_as_ushort(hb);
    l = __bfloat16_as_ushort(__float2bfloat16_rn(y - __bfloat162float(hb)));
}
__device__ __forceinline__ float bil(const float* f, int o00, int o01, int o10, int o11,
                                     float fx, float fy) {
    float va = fmaf(fx, f[o01] - f[o00], f[o00]);
    float vb = fmaf(fx, f[o11] - f[o10], f[o10]);
    return fmaf(fy, vb - va, va);
}
__device__ __forceinline__ void mk64(float gx, float gy, int Ws, int Hs, int p,
                                     int* o, float* w) {
    float xf = fmaf(gx + 1.f, 0.5f * (float)Ws, -0.5f);
    float yf = fmaf(gy + 1.f, 0.5f * (float)Hs, -0.5f);
    float x0f = floorf(xf), y0f = floorf(yf);
    int x0 = (int)x0f, y0 = (int)y0f;
    int ix0 = min(max(x0, 0), Ws - 1), ix1 = min(max(x0 + 1, 0), Ws - 1);
    int iy0 = min(max(y0, 0), Hs - 1), iy1 = min(max(y0 + 1, 0), Hs - 1);
    o[p] = iy0 * Ws + ix0;       o[64 + p] = iy0 * Ws + ix1;
    o[128 + p] = iy1 * Ws + ix0; o[192 + p] = iy1 * Ws + ix1;
    w[p] = xf - x0f;  w[64 + p] = yf - y0f;
}
__device__ __forceinline__ void ldm4(u32* r, u32 a) {
    asm volatile("ldmatrix.sync.aligned.m8n8.x4.shared.b16 {%0,%1,%2,%3}, [%4];"
                 : "=r"(r[0]), "=r"(r[1]), "=r"(r[2]), "=r"(r[3]) : "r"(a));
}
__device__ __forceinline__ void ldm2(u32* r, u32 a) {
    asm volatile("ldmatrix.sync.aligned.m8n8.x2.shared.b16 {%0,%1}, [%2];"
                 : "=r"(r[0]), "=r"(r[1]) : "r"(a));
}
__device__ __forceinline__ void mma(float* d, const u32* a, const u32* b) {
    asm volatile("mma.sync.aligned.m16n8k16.row.col.f32.bf16.bf16.f32 "
                 "{%0,%1,%2,%3}, {%4,%5,%6,%7}, {%8,%9}, {%0,%1,%2,%3};"
                 : "+f"(d[0]), "+f"(d[1]), "+f"(d[2]), "+f"(d[3])
                 : "r"(a[0]), "r"(a[1]), "r"(a[2]), "r"(a[3]), "r"(b[0]), "r"(b[1]));
}
__device__ __forceinline__ void stage(u32 sdst, const unsigned char* src, int bytes) {
    for (int i = threadIdx.x * 16; i < bytes; i += NTH * 16)
        asm volatile("cp.async.cg.shared.global [%0], [%1], 16;"
                     :: "r"(sdst + i), "l"(src + i));
    asm volatile("cp.async.commit_group;" ::: "memory");
}

// ---------------- prep: W[k][n] -> sub-chunk images, SW128, hi|lo rows ------
__global__ void prep_kernel(const float* w0, const float* w1, const float* w2,
                            const float* w3, const float* w4, const float* w5,
                            const float* w6, const float* w7, const float* w8)
{
    const int L = blockIdx.x;
    const float* W; int K, KP, N; u32 off;
    switch (L) {
        case 0: W = w0; K = 64;  KP = 64;  N = 128; off = 0;       break;
        case 1: W = w1; K = 128; KP = 128; N = 256; off = 32768;   break;
        case 2: W = w2; K = 256; KP = 256; N = 128; off = 163840;  break;
        case 3: W = w3; K = 128; KP = 128; N = 128; off = 294912;  break;
        case 4: W = w4; K = 128; KP = 128; N = 256; off = 360448;  break;
        case 5: W = w5; K = 256; KP = 256; N = 128; off = 491520;  break;
        case 6: W = w6; K = 260; KP = 288; N = 256; off = 622592;  break;
        case 7: W = w7; K = 256; KP = 256; N = 128; off = 917504;  break;
        default:W = w8; K = 128; KP = 128; N = 64;  off = 1048576; break;
    }
    const int SC = (N < 128) ? N : 128;
    const int NH = N / SC;
    for (int idx = threadIdx.x; idx < KP * N; idx += blockDim.x) {
        int k = idx / N, n = idx % N;
        float w = (k < K) ? W[(size_t)k * N + n] : 0.f;
        u16 h, l; split_bf(w, h, l);
        int c = k >> 5, kk = k & 31;
        int half = n / SC, np = n % SC;
        int s = c * NH + half;
        size_t base = (size_t)off + (size_t)s * ((size_t)SC * 128);
        u32 b = (u32)(np * 128 + (kk >> 3) * 16 + (kk & 7) * 2);
        *(u16*)(g_wsc + base + swz(b)) = h;
        *(u16*)(g_wsc + base + swz(b + 64)) = l;
    }
}

// ---------------- MMA on one 16KB sub-chunk ---------------------------------
template<int SC, int NH, int HALF, int NT4>
__device__ __forceinline__ void mma_sub(u32 sb, u32 aih, u32 ail, u32 bbase, int c,
                                        int mi, int ni, int arow, int akol,
                                        int brow, int bkol,
                                        float (&acc)[2][NH][NT4][4])
{
    #pragma unroll
    for (int kt = 0; kt < 2; ++kt) {
        u32 ahi[2][4], alo[2][4];
        #pragma unroll
        for (int mt = 0; mt < 2; ++mt) {
            u32 aoff = (u32)(((mi * 32 + mt * 16 + arow) * SA + c * 32 + kt * 16 + akol) * 2);
            ldm4(ahi[mt], sb + aih + aoff);
            ldm4(alo[mt], sb + ail + aoff);
        }
        #pragma unroll
        for (int nt = 0; nt < NT4; ++nt) {
            const int nn = ni * (SC / 4) + nt * 8 + brow;
            const int q = kt * 2 + (bkol >> 3);
            u32 bhi[2], blo[2];
            ldm2(bhi, bbase + swz((u32)(nn * 128 + q * 16)));
            ldm2(blo, bbase + swz((u32)(nn * 128 + 64 + q * 16)));
            #pragma unroll
            for (int mt = 0; mt < 2; ++mt) {
                mma(acc[mt][HALF][nt], ahi[mt], bhi);
                mma(acc[mt][HALF][nt], alo[mt], bhi);
                mma(acc[mt][HALF][nt], ahi[mt], blo);
            }
        }
    }
}

// ---------------- one dense layer, cp.async pipelined -----------------------
// MODE: 0 bias, 1 gelu, 2 relu, 3 residual(F)+sigmoid(gate)
template<int KP, int N, int MODE>
__device__ __forceinline__ void run_layer(char* smc, u32 sb,
    const unsigned char* gW, const unsigned char* nextW, int nextSB, int& gq,
    u32 aih, u32 ail, u32 aoh, u32 aol,
    const float* __restrict__ bias, const float* __restrict__ gate)
{
    constexpr int SC = (N < 128) ? N : 128;
    constexpr int NH = N / SC;
    constexpr int CH = KP / 32;
    constexpr int S  = CH * NH;
    constexpr int SB = SC * 128;
    constexpr int NT4 = SC / 32;

    const int tid = threadIdx.x, w = tid >> 5, lane = tid & 31;
    const int mi = w & 1, ni = w >> 1;
    const int arow = (lane & 7) + ((lane >> 3) & 1) * 8;
    const int akol = (lane >> 4) * 8;
    const int bl = lane & 15, brow = bl & 7, bkol = (bl >> 3) * 8;
    const int p0 = (gq - 1) & 1;

    float acc[2][NH][NT4][4];
    #pragma unroll
    for (int mt = 0; mt < 2; ++mt)
        #pragma unroll
        for (int hh = 0; hh < NH; ++hh)
            #pragma unroll
            for (int nt = 0; nt < NT4; ++nt)
                #pragma unroll
                for (int q = 0; q < 4; ++q) acc[mt][hh][nt][q] = 0.f;

    for (int s = 0; s < S; ++s) {
        asm volatile("cp.async.wait_group 0;" ::: "memory");
        __syncthreads();
        if (s + 1 < S) {
            stage(sb + OFF_B0 + (gq & 1) * BUFSZ, gW + (size_t)(s + 1) * SB, SB);
            ++gq;
        } else if (nextW) {
            stage(sb + OFF_B0 + (gq & 1) * BUFSZ, nextW, nextSB);
            ++gq;
        }
        const u32 bbase = sb + OFF_B0 + (u32)(((p0 + s) & 1) * BUFSZ);
        const int c = s / NH;
        if (NH == 1 || (s - c * NH) == 0)
            mma_sub<SC, NH, 0, NT4>(sb, aih, ail, bbase, c, mi, ni, arow, akol, brow, bkol, acc);
        else
            mma_sub<SC, NH, (NH > 1 ? 1 : 0), NT4>(sb, aih, ail, bbase, c, mi, ni, arow, akol, brow, bkol, acc);
    }

    // epilogue straight from registers
    const int colg = (lane & 3) * 2, rowg = lane >> 2;
    #pragma unroll
    for (int mt = 0; mt < 2; ++mt) {
        #pragma unroll
        for (int hh = 0; hh < NH; ++hh) {
            #pragma unroll
            for (int nt = 0; nt < NT4; ++nt) {
                const int n0 = hh * SC + ni * (SC / 4) + nt * 8 + colg;
                const float b0 = __ldg(bias + n0), b1 = __ldg(bias + n0 + 1);
                float s0 = 0.f, s1 = 0.f;
                if (MODE == 3) {
                    s0 = 1.f / (1.f + expf(-__ldg(gate + n0)));
                    s1 = 1.f / (1.f + expf(-__ldg(gate + n0 + 1)));
                }
                #pragma unroll
                for (int h = 0; h < 2; ++h) {
                    const int r = mi * 32 + mt * 16 + rowg + h * 8;
                    float v0 = acc[mt][hh][nt][2 * h]     + b0;
                    float v1 = acc[mt][hh][nt][2 * h + 1] + b1;
                    if (MODE == 1) {
                        v0 = 0.5f * v0 * (1.f + erff(v0 * 0.70710678118654752f));
                        v1 = 0.5f * v1 * (1.f + erff(v1 * 0.70710678118654752f));
                    } else if (MODE == 2) {
                        v0 = fmaxf(v0, 0.f); v1 = fmaxf(v1, 0.f);
                    } else if (MODE == 3) {
                        float2 rr = *(const float2*)((const float*)(smc + OFF_F) + r * FST + n0);
                        v0 = rr.x + s0 * v0; v1 = rr.y + s1 * v1;
                    }
                    u16 h0, l0, h1, l1;
                    split_bf(v0, h0, l0); split_bf(v1, h1, l1);
                    *(u32*)(smc + aoh + (r * SA + n0) * 2) = (u32)h0 | ((u32)h1 << 16);
                    *(u32*)(smc + aol + (r * SA + n0) * 2) = (u32)l0 | ((u32)l1 << 16);
                }
            }
        }
    }
}

// ---- sampling writers ------------------------------------------------------
template<int C, int HWs>
__device__ __forceinline__ void samp_split(const float* __restrict__ fm,
                                           const int* o, const float* w,
                                           char* smc, u32 dh, u32 dl, int coff)
{
    for (int t = threadIdx.x; t < C * 64; t += NTH) {
        int p = t & 63, c = t >> 6;
        float v = bil(fm + (size_t)c * HWs, o[p], o[64 + p], o[128 + p], o[192 + p],
                      w[p], w[64 + p]);
        u16 h, l; split_bf(v, h, l);
        *(u16*)(smc + dh + (p * SA + coff + c) * 2) = h;
        *(u16*)(smc + dl + (p * SA + coff + c) * 2) = l;
    }
}
template<int C, int HWs>
__device__ __forceinline__ void samp_f32(const float* __restrict__ fm,
                                         const int* o, const float* w, float* F)
{
    for (int t = threadIdx.x; t < C * 64; t += NTH) {
        int p = t & 63, c = t >> 6;
        F[p * FST + c] = bil(fm + (size_t)c * HWs, o[p], o[64 + p], o[128 + p], o[192 + p],
                             w[p], w[64 + p]);
    }
}

// ---------------- main kernel -----------------------------------------------
__global__ __launch_bounds__(NTH, 1)
void ifd_kernel(const float* __restrict__ feat_s8,  const float* __restrict__ feat1_s8,
                const float* __restrict__ feat_s16, const float* __restrict__ ctx_s8,
                const float* __restrict__ coarse_flow,
                const float* __restrict__ pcb,  const float* __restrict__ gate1,
                const float* __restrict__ f1b1, const float* __restrict__ f1b2,
                const float* __restrict__ psb,  const float* __restrict__ gate2,
                const float* __restrict__ f2b1, const float* __restrict__ f2b2,
                const float* __restrict__ hb0,  const float* __restrict__ hb1,
                const float* __restrict__ hb2,  const float* __restrict__ hw3,
                const float* __restrict__ hb3,  float* __restrict__ out)
{
    extern __shared__ char smc[];
    const u32 sb = s2u(smc);
    const int tid = threadIdx.x;

    // kick off L0 sub0 immediately (overlaps all of phase 0 + sampling)
    stage(sb + OFF_B0, g_wsc, BUFSZ);
    int gq = 1;

    int*   s8o  = (int*)(smc + OFF_AUX);
    float* s8w  = (float*)(smc + OFF_AUX + 1024);
    int*   s16o = (int*)(smc + OFF_AUX + 1536);
    float* s16w = (float*)(smc + OFF_AUX + 2560);
    int*   wro  = (int*)(smc + OFF_AUX + 3072);
    float* wrw  = (float*)(smc + OFF_AUX + 4096);
    float* cqx  = (float*)(smc + OFF_AUX + 4608);
    float* cqy  = (float*)(smc + OFF_AUX + 4864);
    float* F    = (float*)(smc + OFF_F);

    const int blk = blockIdx.x;
    const int b = (blk >= 3072) ? 1 : 0;
    const int t = blk - b * 3072;
    const int yrow = t >> 3, xbase = (t & 7) << 6;

    const float* f8b  = feat_s8     + (size_t)b * 128 * 3072;
    const float* f1bp = feat1_s8    + (size_t)b * 128 * 3072;
    const float* f16b = feat_s16    + (size_t)b * 128 * 768;
    const float* cxb  = ctx_s8      + (size_t)b * 64 * 3072;
    const float* cfb  = coarse_flow + (size_t)b * 2 * 3072;

    // ---- phase 0 -----------------------------------------------------------
    if (tid < 64) {
        const int p = tid;
        const float lim = 1.f - 1e-6f;
        float gx = (2.f * (float)(xbase + p) + 1.f) * (1.f / 512.f) - 1.f;
        float gy = (2.f * (float)yrow + 1.f) * (1.f / 384.f) - 1.f;
        gx = fminf(fmaxf(gx, -lim), lim);
        gy = fminf(fmaxf(gy, -lim), lim);
        mk64(gx, gy, 64, 48, p, s8o, s8w);
        mk64(gx, gy, 32, 24, p, s16o, s16w);
        float fx = s8w[p], fy = s8w[64 + p];
        int o00 = s8o[p], o01 = s8o[64 + p], o10 = s8o[128 + p], o11 = s8o[192 + p];
        float c0 = bil(cfb, o00, o01, o10, o11, fx, fy);
        float c1 = bil(cfb + 3072, o00, o01, o10, o11, fx, fy);
        float qx = 8.f * c0, qy = 8.f * c1;
        cqx[p] = qx; cqy[p] = qy;
        float wx = fminf(fmaxf(gx + qx * (2.f / 512.f), -lim), lim);
        float wy = fminf(fmaxf(gy + qy * (2.f / 384.f), -lim), lim);
        mk64(wx, wy, 64, 48, p, wro, wrw);
        float tv[4] = { gx, gy, qx * (1.f / 512.f), qy * (1.f / 384.f) };
        #pragma unroll
        for (int v = 0; v < 4; ++v) {
            u16 h, l; split_bf(tv[v], h, l);
            *(u16*)(smc + OFF_A0H + (p * SA + 256 + v) * 2) = h;
            *(u16*)(smc + OFF_A0L + (p * SA + 256 + v) * 2) = l;
        }
        for (int c = 260; c < 288; c += 2) {
            *(u32*)(smc + OFF_A0H + (p * SA + c) * 2) = 0;
            *(u32*)(smc + OFF_A0L + (p * SA + c) * 2) = 0;
        }
    }
    __syncthreads();

    samp_split<64, 3072>(cxb, s8o, s8w, smc, OFF_A0H, OFF_A0L, 0);  // fctx -> A0
    samp_f32<128, 3072>(f8b, s8o, s8w, F);                           // f8 -> F

    run_layer< 64, 128, 3>(smc, sb, g_wsc + 0,      g_wsc + 32768,  BUFSZ, gq,
                           OFF_A0H, OFF_A0L, OFF_A1H, OFF_A1L, pcb,  gate1);
    samp_f32<128, 768>(f16b, s16o, s16w, F);                         // f16 -> F
    run_layer<128, 256, 1>(smc, sb, g_wsc + 32768,  g_wsc + 163840, BUFSZ, gq,
                           OFF_A1H, OFF_A1L, OFF_A0H, OFF_A0L, f1b1, 0);
    run_layer<256, 128, 0>(smc, sb, g_wsc + 163840, g_wsc + 294912, BUFSZ, gq,
                           OFF_A0H, OFF_A0L, OFF_A1H, OFF_A1L, f1b2, 0);
    __syncthreads();                                                 // all A0 reads done
    samp_split<128, 3072>(f1bp, wro, wrw, smc, OFF_A0H, OFF_A0L, 128); // f1w -> A0[128..255]
    run_layer<128, 128, 3>(smc, sb, g_wsc + 294912, g_wsc + 360448, BUFSZ, gq,
                           OFF_A1H, OFF_A1L, OFF_A0H, OFF_A0L, psb,  gate2);
    run_layer<128, 256, 1>(smc, sb, g_wsc + 360448, g_wsc + 491520, BUFSZ, gq,
                           OFF_A0H, OFF_A0L, OFF_A1H, OFF_A1L, f2b1, 0);
    run_layer<256, 128, 0>(smc, sb, g_wsc + 491520, g_wsc + 622592, BUFSZ, gq,
                           OFF_A1H, OFF_A1L, OFF_A0H, OFF_A0L, f2b2, 0);
    // A0 = [fused | f1w | tail | zeros]
    run_layer<288, 256, 2>(smc, sb, g_wsc + 622592, g_wsc + 917504, BUFSZ, gq,
                           OFF_A0H, OFF_A0L, OFF_A1H, OFF_A1L, hb0, 0);
    run_layer<256, 128, 2>(smc, sb, g_wsc + 917504, g_wsc + 1048576, 8192, gq,
                           OFF_A1H, OFF_A1L, OFF_A0H, OFF_A0L, hb1, 0);
    run_layer<128,  64, 2>(smc, sb, g_wsc + 1048576, (const unsigned char*)0, 0, gq,
                           OFF_A0H, OFF_A0L, OFF_A1H, OFF_A1L, hb2, 0);
    __syncthreads();

    // ---- final 64->2 + flow assembly (h in A1 cols 0..63) ------------------
    if (tid < 128) {
        const int p = tid & 63, ch = tid >> 6;
        float acc = __ldg(hb3 + ch);
        #pragma unroll
        for (int k2 = 0; k2 < 32; ++k2) {
            u32 H = *(const u32*)(smc + OFF_A1H + (p * SA + 2 * k2) * 2);
            u32 L = *(const u32*)(smc + OFF_A1L + (p * SA + 2 * k2) * 2);
            float x0 = __bfloat162float(__ushort_as_bfloat16((u16)(H & 0xffff)))
                     + __bfloat162float(__ushort_as_bfloat16((u16)(L & 0xffff)));
            float x1 = __bfloat162float(__ushort_as_bfloat16((u16)(H >> 16)))
                     + __bfloat162float(__ushort_as_bfloat16((u16)(L >> 16)));
            acc = fmaf(x0, __ldg(hw3 + 4 * k2 + ch), acc);
            acc = fmaf(x1, __ldg(hw3 + 4 * k2 + 2 + ch), acc);
        }
        float fl = ch ? (cqy[p] + acc * 384.f) : (cqx[p] + acc * 512.f);
        out[(((size_t)(b * 2 + ch)) * 384 + yrow) * 512 + (xbase + p)] = fl;
    }
}

extern "C" void kernel_launch(void* const* d_in, const int* in_sizes, int n_in,
                              void* d_out, int out_size)
{
    const float* feat_s8     = (const float*)d_in[1];
    const float* feat1_s8    = (const float*)d_in[2];
    const float* feat_s16    = (const float*)d_in[3];
    const float* ctx_s8      = (const float*)d_in[4];
    const float* coarse_flow = (const float*)d_in[5];
    const float* proj_ctx_w  = (const float*)d_in[6];
    const float* proj_ctx_b  = (const float*)d_in[7];
    const float* gate1       = (const float*)d_in[8];
    const float* ffn1_w1     = (const float*)d_in[9];
    const float* ffn1_b1     = (const float*)d_in[10];
    const float* ffn1_w2     = (const float*)d_in[11];
    const float* ffn1_b2     = (const float*)d_in[12];
    const float* proj_s8_w   = (const float*)d_in[13];
    const float* proj_s8_b   = (const float*)d_in[14];
    const float* gate2       = (const float*)d_in[15];
    const float* ffn2_w1     = (const float*)d_in[16];
    const float* ffn2_b1     = (const float*)d_in[17];
    const float* ffn2_w2     = (const float*)d_in[18];
    const float* ffn2_b2     = (const float*)d_in[19];
    const float* hw0 = (const float*)d_in[20];
    const float* hb0 = (const float*)d_in[21];
    const float* hw1 = (const float*)d_in[22];
    const float* hb1 = (const float*)d_in[23];
    const float* hw2 = (const float*)d_in[24];
    const float* hb2 = (const float*)d_in[25];
    const float* hw3 = (const float*)d_in[26];
    const float* hb3 = (const float*)d_in[27];

    prep_kernel<<<9, 256>>>(proj_ctx_w, ffn1_w1, ffn1_w2, proj_s8_w, ffn2_w1,
                            ffn2_w2, hw0, hw1, hw2);

    cudaFuncSetAttribute(ifd_kernel, cudaFuncAttributeMaxDynamicSharedMemorySize, SM_TOTAL);
    ifd_kernel<<<6144, NTH, SM_TOTAL>>>(
        feat_s8, feat1_s8, feat_s16, ctx_s8, coarse_flow,
        proj_ctx_b, gate1, ffn1_b1, ffn1_b2, proj_s8_b, gate2,
        ffn2_b1, ffn2_b2, hb0, hb1, hb2, hw3, hb3, (float*)d_out);
}

// round 17
// speedup vs baseline: 3.2100x; 1.2139x over previous
#include <cuda_runtime.h>
#include <cuda_bf16.h>
#include <math.h>

typedef unsigned int u32;
typedef unsigned short u16;

#define NTH 512
#define SA 296                      // A row stride (bf16 elements)
#define OFF_A0H 0
#define OFF_A0L 37888
#define OFF_A1H 75776
#define OFF_A1L 113664
#define OFF_B0  151552              // two 16KB B staging buffers
#define BUFSZ   16384
#define OFF_F   184320              // fp32 residual buffer [64][132]
#define FST 132
#define OFF_AUX 218112
#define SM_TOTAL 223232

__device__ __align__(16) unsigned char g_wsc[1081344];

// ---------------- helpers ---------------------------------------------------
__device__ __forceinline__ u32 swz(u32 o) { return o ^ ((o >> 3) & 0x70); }
__device__ __forceinline__ u32 s2u(const void* p) {
    u32 a;
    asm("{ .reg .u64 t; cvta.to.shared.u64 t, %1; cvt.u32.u64 %0, t; }" : "=r"(a) : "l"(p));
    return a;
}
__device__ __forceinline__ void split_bf(float y, u16& h, u16& l) {
    __nv_bfloat16 hb = __float2bfloat16_rn(y);
    h = __bfloat16_as_ushort(hb);
    l = __bfloat16_as_ushort(__float2bfloat16_rn(y - __bfloat162float(hb)));
}
__device__ __forceinline__ float bil(const float* f, int o00, int o01, int o10, int o11,
                                     float fx, float fy) {
    float va = fmaf(fx, f[o01] - f[o00], f[o00]);
    float vb = fmaf(fx, f[o11] - f[o10], f[o10]);
    return fmaf(fy, vb - va, va);
}
__device__ __forceinline__ void mk64(float gx, float gy, int Ws, int Hs, int p,
                                     int* o, float* w) {
    float xf = fmaf(gx + 1.f, 0.5f * (float)Ws, -0.5f);
    float yf = fmaf(gy + 1.f, 0.5f * (float)Hs, -0.5f);
    float x0f = floorf(xf), y0f = floorf(yf);
    int x0 = (int)x0f, y0 = (int)y0f;
    int ix0 = min(max(x0, 0), Ws - 1), ix1 = min(max(x0 + 1, 0), Ws - 1);
    int iy0 = min(max(y0, 0), Hs - 1), iy1 = min(max(y0 + 1, 0), Hs - 1);
    o[p] = iy0 * Ws + ix0;       o[64 + p] = iy0 * Ws + ix1;
    o[128 + p] = iy1 * Ws + ix0; o[192 + p] = iy1 * Ws + ix1;
    w[p] = xf - x0f;  w[64 + p] = yf - y0f;
}
__device__ __forceinline__ void ldm4(u32* r, u32 a) {
    asm volatile("ldmatrix.sync.aligned.m8n8.x4.shared.b16 {%0,%1,%2,%3}, [%4];"
                 : "=r"(r[0]), "=r"(r[1]), "=r"(r[2]), "=r"(r[3]) : "r"(a));
}
__device__ __forceinline__ void ldm2(u32* r, u32 a) {
    asm volatile("ldmatrix.sync.aligned.m8n8.x2.shared.b16 {%0,%1}, [%2];"
                 : "=r"(r[0]), "=r"(r[1]) : "r"(a));
}
__device__ __forceinline__ void mma(float* d, const u32* a, const u32* b) {
    asm volatile("mma.sync.aligned.m16n8k16.row.col.f32.bf16.bf16.f32 "
                 "{%0,%1,%2,%3}, {%4,%5,%6,%7}, {%8,%9}, {%0,%1,%2,%3};"
                 : "+f"(d[0]), "+f"(d[1]), "+f"(d[2]), "+f"(d[3])
                 : "r"(a[0]), "r"(a[1]), "r"(a[2]), "r"(a[3]), "r"(b[0]), "r"(b[1]));
}
__device__ __forceinline__ void stage(u32 sdst, const unsigned char* src, int bytes) {
    for (int i = threadIdx.x * 16; i < bytes; i += NTH * 16)
        asm volatile("cp.async.cg.shared.global [%0], [%1], 16;"
                     :: "r"(sdst + i), "l"(src + i));
    asm volatile("cp.async.commit_group;" ::: "memory");
}

// ---------------- prep: W[k][n] -> sub-chunk images, SW128, hi|lo rows ------
__global__ void prep_kernel(const float* w0, const float* w1, const float* w2,
                            const float* w3, const float* w4, const float* w5,
                            const float* w6, const float* w7, const float* w8)
{
    const int L = blockIdx.x;
    const float* W; int K, KP, N; u32 off;
    switch (L) {
        case 0: W = w0; K = 64;  KP = 64;  N = 128; off = 0;       break;
        case 1: W = w1; K = 128; KP = 128; N = 256; off = 32768;   break;
        case 2: W = w2; K = 256; KP = 256; N = 128; off = 163840;  break;
        case 3: W = w3; K = 128; KP = 128; N = 128; off = 294912;  break;
        case 4: W = w4; K = 128; KP = 128; N = 256; off = 360448;  break;
        case 5: W = w5; K = 256; KP = 256; N = 128; off = 491520;  break;
        case 6: W = w6; K = 260; KP = 288; N = 256; off = 622592;  break;
        case 7: W = w7; K = 256; KP = 256; N = 128; off = 917504;  break;
        default:W = w8; K = 128; KP = 128; N = 64;  off = 1048576; break;
    }
    const int SC = (N < 128) ? N : 128;
    const int NH = N / SC;
    for (int idx = threadIdx.x; idx < KP * N; idx += blockDim.x) {
        int k = idx / N, n = idx % N;
        float w = (k < K) ? W[(size_t)k * N + n] : 0.f;
        u16 h, l; split_bf(w, h, l);
        int c = k >> 5, kk = k & 31;
        int half = n / SC, np = n % SC;
        int s = c * NH + half;
        size_t base = (size_t)off + (size_t)s * ((size_t)SC * 128);
        u32 b = (u32)(np * 128 + (kk >> 3) * 16 + (kk & 7) * 2);
        *(u16*)(g_wsc + base + swz(b)) = h;
        *(u16*)(g_wsc + base + swz(b + 64)) = l;
    }
}

// ---------------- MMA on one 16/8KB sub-chunk (16-warp layout) --------------
template<int SC, int NH, int HALF, int NTS>
__device__ __forceinline__ void mma_sub(u32 sb, u32 aih, u32 ail, u32 bbase, int c,
                                        int mi, int ni, int arow, int akol,
                                        int brow, int bkol,
                                        float (&acc)[2][NH][NTS][4])
{
    #pragma unroll
    for (int kt = 0; kt < 2; ++kt) {
        u32 ahi[2][4], alo[2][4];
        #pragma unroll
        for (int mt = 0; mt < 2; ++mt) {
            u32 aoff = (u32)(((mi * 32 + mt * 16 + arow) * SA + c * 32 + kt * 16 + akol) * 2);
            ldm4(ahi[mt], sb + aih + aoff);
            ldm4(alo[mt], sb + ail + aoff);
        }
        #pragma unroll
        for (int nt = 0; nt < NTS; ++nt) {
            const int nn = ni * (SC / 8) + nt * 8 + brow;
            const int q = kt * 2 + (bkol >> 3);
            u32 bhi[2], blo[2];
            ldm2(bhi, bbase + swz((u32)(nn * 128 + q * 16)));
            ldm2(blo, bbase + swz((u32)(nn * 128 + 64 + q * 16)));
            #pragma unroll
            for (int mt = 0; mt < 2; ++mt) {
                mma(acc[mt][HALF][nt], ahi[mt], bhi);
                mma(acc[mt][HALF][nt], alo[mt], bhi);
                mma(acc[mt][HALF][nt], ahi[mt], blo);
            }
        }
    }
}

// ---------------- one dense layer, cp.async pipelined -----------------------
// MODE: 0 bias, 1 gelu, 2 relu, 3 residual(F)+sigmoid(gate)
template<int KP, int N, int MODE>
__device__ __forceinline__ void run_layer(char* smc, u32 sb,
    const unsigned char* gW, const unsigned char* nextW, int nextSB, int& gq,
    u32 aih, u32 ail, u32 aoh, u32 aol,
    const float* __restrict__ bias, const float* __restrict__ gate)
{
    constexpr int SC = (N < 128) ? N : 128;
    constexpr int NH = N / SC;
    constexpr int CH = KP / 32;
    constexpr int S  = CH * NH;
    constexpr int SB = SC * 128;
    constexpr int NTS = SC / 64;                // 8-col tiles per warp slice

    const int tid = threadIdx.x, w = tid >> 5, lane = tid & 31;
    const int mi = w & 1, ni = w >> 1;          // 2 m-halves x 8 n-slices
    const int arow = (lane & 7) + ((lane >> 3) & 1) * 8;
    const int akol = (lane >> 4) * 8;
    const int bl = lane & 15, brow = bl & 7, bkol = (bl >> 3) * 8;
    const int p0 = (gq - 1) & 1;

    float acc[2][NH][NTS][4];
    #pragma unroll
    for (int mt = 0; mt < 2; ++mt)
        #pragma unroll
        for (int hh = 0; hh < NH; ++hh)
            #pragma unroll
            for (int nt = 0; nt < NTS; ++nt)
                #pragma unroll
                for (int q = 0; q < 4; ++q) acc[mt][hh][nt][q] = 0.f;

    for (int s = 0; s < S; ++s) {
        asm volatile("cp.async.wait_group 0;" ::: "memory");
        __syncthreads();
        if (s + 1 < S) {
            stage(sb + OFF_B0 + (gq & 1) * BUFSZ, gW + (size_t)(s + 1) * SB, SB);
            ++gq;
        } else if (nextW) {
            stage(sb + OFF_B0 + (gq & 1) * BUFSZ, nextW, nextSB);
            ++gq;
        }
        const u32 bbase = sb + OFF_B0 + (u32)(((p0 + s) & 1) * BUFSZ);
        const int c = s / NH;
        if (NH == 1 || (s - c * NH) == 0)
            mma_sub<SC, NH, 0, NTS>(sb, aih, ail, bbase, c, mi, ni, arow, akol, brow, bkol, acc);
        else
            mma_sub<SC, NH, (NH > 1 ? 1 : 0), NTS>(sb, aih, ail, bbase, c, mi, ni, arow, akol, brow, bkol, acc);
    }

    // epilogue straight from registers
    const int colg = (lane & 3) * 2, rowg = lane >> 2;
    #pragma unroll
    for (int mt = 0; mt < 2; ++mt) {
        #pragma unroll
        for (int hh = 0; hh < NH; ++hh) {
            #pragma unroll
            for (int nt = 0; nt < NTS; ++nt) {
                const int n0 = hh * SC + ni * (SC / 8) + nt * 8 + colg;
                const float b0 = __ldg(bias + n0), b1 = __ldg(bias + n0 + 1);
                float s0 = 0.f, s1 = 0.f;
                if (MODE == 3) {
                    s0 = 1.f / (1.f + expf(-__ldg(gate + n0)));
                    s1 = 1.f / (1.f + expf(-__ldg(gate + n0 + 1)));
                }
                #pragma unroll
                for (int h = 0; h < 2; ++h) {
                    const int r = mi * 32 + mt * 16 + rowg + h * 8;
                    float v0 = acc[mt][hh][nt][2 * h]     + b0;
                    float v1 = acc[mt][hh][nt][2 * h + 1] + b1;
                    if (MODE == 1) {
                        v0 = 0.5f * v0 * (1.f + erff(v0 * 0.70710678118654752f));
                        v1 = 0.5f * v1 * (1.f + erff(v1 * 0.70710678118654752f));
                    } else if (MODE == 2) {
                        v0 = fmaxf(v0, 0.f); v1 = fmaxf(v1, 0.f);
                    } else if (MODE == 3) {
                        float2 rr = *(const float2*)((const float*)(smc + OFF_F) + r * FST + n0);
                        v0 = rr.x + s0 * v0; v1 = rr.y + s1 * v1;
                    }
                    u16 h0, l0, h1, l1;
                    split_bf(v0, h0, l0); split_bf(v1, h1, l1);
                    *(u32*)(smc + aoh + (r * SA + n0) * 2) = (u32)h0 | ((u32)h1 << 16);
                    *(u32*)(smc + aol + (r * SA + n0) * 2) = (u32)l0 | ((u32)l1 << 16);
                }
            }
        }
    }
}

// ---- sampling writers ------------------------------------------------------
template<int C, int HWs>
__device__ __forceinline__ void samp_split(const float* __restrict__ fm,
                                           const int* o, const float* w,
                                           char* smc, u32 dh, u32 dl, int coff)
{
    for (int t = threadIdx.x; t < C * 64; t += NTH) {
        int p = t & 63, c = t >> 6;
        float v = bil(fm + (size_t)c * HWs, o[p], o[64 + p], o[128 + p], o[192 + p],
                      w[p], w[64 + p]);
        u16 h, l; split_bf(v, h, l);
        *(u16*)(smc + dh + (p * SA + coff + c) * 2) = h;
        *(u16*)(smc + dl + (p * SA + coff + c) * 2) = l;
    }
}
template<int C, int HWs>
__device__ __forceinline__ void samp_f32(const float* __restrict__ fm,
                                         const int* o, const float* w, float* F)
{
    for (int t = threadIdx.x; t < C * 64; t += NTH) {
        int p = t & 63, c = t >> 6;
        F[p * FST + c] = bil(fm + (size_t)c * HWs, o[p], o[64 + p], o[128 + p], o[192 + p],
                             w[p], w[64 + p]);
    }
}

// ---------------- main kernel -----------------------------------------------
__global__ __launch_bounds__(NTH, 1)
void ifd_kernel(const float* __restrict__ feat_s8,  const float* __restrict__ feat1_s8,
                const float* __restrict__ feat_s16, const float* __restrict__ ctx_s8,
                const float* __restrict__ coarse_flow,
                const float* __restrict__ pcb,  const float* __restrict__ gate1,
                const float* __restrict__ f1b1, const float* __restrict__ f1b2,
                const float* __restrict__ psb,  const float* __restrict__ gate2,
                const float* __restrict__ f2b1, const float* __restrict__ f2b2,
                const float* __restrict__ hb0,  const float* __restrict__ hb1,
                const float* __restrict__ hb2,  const float* __restrict__ hw3,
                const float* __restrict__ hb3,  float* __restrict__ out)
{
    extern __shared__ char smc[];
    const u32 sb = s2u(smc);
    const int tid = threadIdx.x;

    // kick off L0 sub0 immediately (overlaps all of phase 0 + sampling)
    stage(sb + OFF_B0, g_wsc, BUFSZ);
    int gq = 1;

    int*   s8o  = (int*)(smc + OFF_AUX);
    float* s8w  = (float*)(smc + OFF_AUX + 1024);
    int*   s16o = (int*)(smc + OFF_AUX + 1536);
    float* s16w = (float*)(smc + OFF_AUX + 2560);
    int*   wro  = (int*)(smc + OFF_AUX + 3072);
    float* wrw  = (float*)(smc + OFF_AUX + 4096);
    float* cqx  = (float*)(smc + OFF_AUX + 4608);
    float* cqy  = (float*)(smc + OFF_AUX + 4864);
    float* F    = (float*)(smc + OFF_F);

    const int blk = blockIdx.x;
    const int b = (blk >= 3072) ? 1 : 0;
    const int t = blk - b * 3072;
    const int yrow = t >> 3, xbase = (t & 7) << 6;

    const float* f8b  = feat_s8     + (size_t)b * 128 * 3072;
    const float* f1bp = feat1_s8    + (size_t)b * 128 * 3072;
    const float* f16b = feat_s16    + (size_t)b * 128 * 768;
    const float* cxb  = ctx_s8      + (size_t)b * 64 * 3072;
    const float* cfb  = coarse_flow + (size_t)b * 2 * 3072;

    // ---- phase 0 -----------------------------------------------------------
    if (tid < 64) {
        const int p = tid;
        const float lim = 1.f - 1e-6f;
        float gx = (2.f * (float)(xbase + p) + 1.f) * (1.f / 512.f) - 1.f;
        float gy = (2.f * (float)yrow + 1.f) * (1.f / 384.f) - 1.f;
        gx = fminf(fmaxf(gx, -lim), lim);
        gy = fminf(fmaxf(gy, -lim), lim);
        mk64(gx, gy, 64, 48, p, s8o, s8w);
        mk64(gx, gy, 32, 24, p, s16o, s16w);
        float fx = s8w[p], fy = s8w[64 + p];
        int o00 = s8o[p], o01 = s8o[64 + p], o10 = s8o[128 + p], o11 = s8o[192 + p];
        float c0 = bil(cfb, o00, o01, o10, o11, fx, fy);
        float c1 = bil(cfb + 3072, o00, o01, o10, o11, fx, fy);
        float qx = 8.f * c0, qy = 8.f * c1;
        cqx[p] = qx; cqy[p] = qy;
        float wx = fminf(fmaxf(gx + qx * (2.f / 512.f), -lim), lim);
        float wy = fminf(fmaxf(gy + qy * (2.f / 384.f), -lim), lim);
        mk64(wx, wy, 64, 48, p, wro, wrw);
        float tv[4] = { gx, gy, qx * (1.f / 512.f), qy * (1.f / 384.f) };
        #pragma unroll
        for (int v = 0; v < 4; ++v) {
            u16 h, l; split_bf(tv[v], h, l);
            *(u16*)(smc + OFF_A0H + (p * SA + 256 + v) * 2) = h;
            *(u16*)(smc + OFF_A0L + (p * SA + 256 + v) * 2) = l;
        }
        for (int c = 260; c < 288; c += 2) {
            *(u32*)(smc + OFF_A0H + (p * SA + c) * 2) = 0;
            *(u32*)(smc + OFF_A0L + (p * SA + c) * 2) = 0;
        }
    }
    __syncthreads();

    samp_split<64, 3072>(cxb, s8o, s8w, smc, OFF_A0H, OFF_A0L, 0);  // fctx -> A0
    samp_f32<128, 3072>(f8b, s8o, s8w, F);                           // f8 -> F

    run_layer< 64, 128, 3>(smc, sb, g_wsc + 0,      g_wsc + 32768,  BUFSZ, gq,
                           OFF_A0H, OFF_A0L, OFF_A1H, OFF_A1L, pcb,  gate1);
    samp_f32<128, 768>(f16b, s16o, s16w, F);                         // f16 -> F
    run_layer<128, 256, 1>(smc, sb, g_wsc + 32768,  g_wsc + 163840, BUFSZ, gq,
                           OFF_A1H, OFF_A1L, OFF_A0H, OFF_A0L, f1b1, 0);
    run_layer<256, 128, 0>(smc, sb, g_wsc + 163840, g_wsc + 294912, BUFSZ, gq,
                           OFF_A0H, OFF_A0L, OFF_A1H, OFF_A1L, f1b2, 0);
    __syncthreads();                                                 // all A0 reads done
    samp_split<128, 3072>(f1bp, wro, wrw, smc, OFF_A0H, OFF_A0L, 128); // f1w -> A0[128..255]
    run_layer<128, 128, 3>(smc, sb, g_wsc + 294912, g_wsc + 360448, BUFSZ, gq,
                           OFF_A1H, OFF_A1L, OFF_A0H, OFF_A0L, psb,  gate2);
    run_layer<128, 256, 1>(smc, sb, g_wsc + 360448, g_wsc + 491520, BUFSZ, gq,
                           OFF_A0H, OFF_A0L, OFF_A1H, OFF_A1L, f2b1, 0);
    run_layer<256, 128, 0>(smc, sb, g_wsc + 491520, g_wsc + 622592, BUFSZ, gq,
                           OFF_A1H, OFF_A1L, OFF_A0H, OFF_A0L, f2b2, 0);
    // A0 = [fused | f1w | tail | zeros]
    run_layer<288, 256, 2>(smc, sb, g_wsc + 622592, g_wsc + 917504, BUFSZ, gq,
                           OFF_A0H, OFF_A0L, OFF_A1H, OFF_A1L, hb0, 0);
    run_layer<256, 128, 2>(smc, sb, g_wsc + 917504, g_wsc + 1048576, 8192, gq,
                           OFF_A1H, OFF_A1L, OFF_A0H, OFF_A0L, hb1, 0);
    run_layer<128,  64, 2>(smc, sb, g_wsc + 1048576, (const unsigned char*)0, 0, gq,
                           OFF_A0H, OFF_A0L, OFF_A1H, OFF_A1L, hb2, 0);
    __syncthreads();

    // ---- final 64->2 + flow assembly (h in A1 cols 0..63) ------------------
    if (tid < 128) {
        const int p = tid & 63, ch = tid >> 6;
        float acc = __ldg(hb3 + ch);
        #pragma unroll
        for (int k2 = 0; k2 < 32; ++k2) {
            u32 H = *(const u32*)(smc + OFF_A1H + (p * SA + 2 * k2) * 2);
            u32 L = *(const u32*)(smc + OFF_A1L + (p * SA + 2 * k2) * 2);
            float x0 = __bfloat162float(__ushort_as_bfloat16((u16)(H & 0xffff)))
                     + __bfloat162float(__ushort_as_bfloat16((u16)(L & 0xffff)));
            float x1 = __bfloat162float(__ushort_as_bfloat16((u16)(H >> 16)))
                     + __bfloat162float(__ushort_as_bfloat16((u16)(L >> 16)));
            acc = fmaf(x0, __ldg(hw3 + 4 * k2 + ch), acc);
            acc = fmaf(x1, __ldg(hw3 + 4 * k2 + 2 + ch), acc);
        }
        float fl = ch ? (cqy[p] + acc * 384.f) : (cqx[p] + acc * 512.f);
        out[(((size_t)(b * 2 + ch)) * 384 + yrow) * 512 + (xbase + p)] = fl;
    }
}

extern "C" void kernel_launch(void* const* d_in, const int* in_sizes, int n_in,
                              void* d_out, int out_size)
{
    const float* feat_s8     = (const float*)d_in[1];
    const float* feat1_s8    = (const float*)d_in[2];
    const float* feat_s16    = (const float*)d_in[3];
    const float* ctx_s8      = (const float*)d_in[4];
    const float* coarse_flow = (const float*)d_in[5];
    const float* proj_ctx_w  = (const float*)d_in[6];
    const float* proj_ctx_b  = (const float*)d_in[7];
    const float* gate1       = (const float*)d_in[8];
    const float* ffn1_w1     = (const float*)d_in[9];
    const float* ffn1_b1     = (const float*)d_in[10];
    const float* ffn1_w2     = (const float*)d_in[11];
    const float* ffn1_b2     = (const float*)d_in[12];
    const float* proj_s8_w   = (const float*)d_in[13];
    const float* proj_s8_b   = (const float*)d_in[14];
    const float* gate2       = (const float*)d_in[15];
    const float* ffn2_w1     = (const float*)d_in[16];
    const float* ffn2_b1     = (const float*)d_in[17];
    const float* ffn2_w2     = (const float*)d_in[18];
    const float* ffn2_b2     = (const float*)d_in[19];
    const float* hw0 = (const float*)d_in[20];
    const float* hb0 = (const float*)d_in[21];
    const float* hw1 = (const float*)d_in[22];
    const float* hb1 = (const float*)d_in[23];
    const float* hw2 = (const float*)d_in[24];
    const float* hb2 = (const float*)d_in[25];
    const float* hw3 = (const float*)d_in[26];
    const float* hb3 = (const float*)d_in[27];

    prep_kernel<<<9, 256>>>(proj_ctx_w, ffn1_w1, ffn1_w2, proj_s8_w, ffn2_w1,
                            ffn2_w2, hw0, hw1, hw2);

    cudaFuncSetAttribute(ifd_kernel, cudaFuncAttributeMaxDynamicSharedMemorySize, SM_TOTAL);
    ifd_kernel<<<6144, NTH, SM_TOTAL>>>(
        feat_s8, feat1_s8, feat_s16, ctx_s8, coarse_flow,
        proj_ctx_b, gate1, ffn1_b1, ffn1_b2, proj_s8_b, gate2,
        ffn2_b1, ffn2_b2, hb0, hb1, hb2, hw3, hb3, (float*)d_out);
}